// round 8
// baseline (speedup 1.0000x reference)
#include <cuda_runtime.h>
#include <cuda_fp16.h>

#define NN 25000
#define NE 400000
#define EE (NE + NN)          // 425000 (edges + self loops)
#define SC 0.35355339059327378f   // 1/sqrt(8)

// ---------------- scratch (static __device__, no allocs) ----------------
__device__ float    g_xall[NN * 4 * 64];   // x_all[N][4][64] fp32
__device__ float2   g_Q[NN * 32];          // per lane dims {2l,2l+1}, pre-scaled by SC
__device__ unsigned g_V1[NN * 32];         // layer-0 V as half2 {v.x*dis, v.y*dis}
__device__ uint4    g_KVab[NN * 32];       // {K_l0, V_l0, K_l1, V_l1} half2 each (V pre-scaled)
__device__ uint2    g_KVc[NN * 32];        // {K_l2, V_l2} half2 each (V pre-scaled)
__device__ float    g_dis[NN];
__device__ int      g_deg[NN];             // invariant: all-zero at kernel_launch entry
__device__ int      g_off[NN + 1];
__device__ int      g_cur[NN];
__device__ int      g_csr[EE];

__device__ __forceinline__ float2 u2f(unsigned u) {
    return __half22float2(*reinterpret_cast<const __half2*>(&u));
}
__device__ __forceinline__ unsigned f2u(float x, float y) {
    __half2 h = __floats2half2_rn(x, y);
    return *reinterpret_cast<unsigned*>(&h);
}

// ---------------- CSR build ----------------
__global__ void k_hist(const int* __restrict__ ei) {
    int e = blockIdx.x * blockDim.x + threadIdx.x;
    if (e < NE) atomicAdd(&g_deg[ei[NE + e]], 1);   // col = ei[1]; self loop implicit +1
}

// single-block scan over NN elements; also computes dis, seeds cur, resets deg
__global__ void k_scan() {
    __shared__ int wsum[32];
    int t = threadIdx.x;
    int lane = t & 31, wid = t >> 5;
    int i0 = t * 25;
    int i1 = i0 + 25 < NN ? i0 + 25 : NN;
    int s = 0;
    for (int i = i0; i < i1; i++) s += g_deg[i] + 1;   // +1 = self loop
    int inc = s;
#pragma unroll
    for (int o = 1; o < 32; o <<= 1) {
        int v = __shfl_up_sync(0xffffffffu, inc, o);
        if (lane >= o) inc += v;
    }
    if (lane == 31) wsum[wid] = inc;
    __syncthreads();
    if (t < 32) {
        int v = wsum[t];
        int inc2 = v;
#pragma unroll
        for (int o = 1; o < 32; o <<= 1) {
            int u = __shfl_up_sync(0xffffffffu, inc2, o);
            if (t >= o) inc2 += u;
        }
        wsum[t] = inc2 - v;   // exclusive
    }
    __syncthreads();
    int run = wsum[wid] + (inc - s);
    for (int i = i0; i < i1; i++) {
        int d = g_deg[i] + 1;
        g_off[i] = run;
        g_cur[i] = run;
        g_dis[i] = rsqrtf((float)d);
        g_deg[i] = 0;          // restore invariant for next replay
        run += d;
    }
    if (t == 0) g_off[NN] = EE;
}

__global__ void k_scatter(const int* __restrict__ ei) {
    int idx = blockIdx.x * blockDim.x + threadIdx.x;
    if (idx >= EE) return;
    int r, c;
    if (idx < NE) { r = ei[idx]; c = ei[NE + idx]; }
    else          { r = c = idx - NE; }               // self loop
    int p = atomicAdd(&g_cur[c], 1);
    g_csr[p] = r;
}

// ---------------- lin1: h = relu(x @ W1 + b1) -> x_all[:,0,:] ----------------
__global__ void k_lin1(const float* __restrict__ x, const float* __restrict__ w,
                       const float* __restrict__ b) {
    int gw = (blockIdx.x * blockDim.x + threadIdx.x) >> 5;
    int lane = threadIdx.x & 31;
    int base = gw * 8;                 // NN % 8 == 0
    if (base >= NN) return;
    const float2* W2 = (const float2*)w;   // [256][32] float2
    float2 acc[8];
#pragma unroll
    for (int n = 0; n < 8; n++) acc[n] = make_float2(0.f, 0.f);
    for (int k0 = 0; k0 < 256; k0 += 32) {
        float xr[8];
#pragma unroll
        for (int n = 0; n < 8; n++) xr[n] = x[(base + n) * 256 + k0 + lane];
#pragma unroll
        for (int kk = 0; kk < 32; kk++) {
            float2 wv = W2[(k0 + kk) * 32 + lane];
#pragma unroll
            for (int n = 0; n < 8; n++) {
                float bv = __shfl_sync(0xffffffffu, xr[n], kk);
                acc[n].x += bv * wv.x;
                acc[n].y += bv * wv.y;
            }
        }
    }
    float2 bb = ((const float2*)b)[lane];
#pragma unroll
    for (int n = 0; n < 8; n++) {
        float2* o = (float2*)&g_xall[((size_t)(base + n) * 4 + 0) * 64];
        o[lane] = make_float2(fmaxf(acc[n].x + bb.x, 0.f), fmaxf(acc[n].y + bb.y, 0.f));
    }
}

// ---------------- QKV helpers ----------------
__device__ __forceinline__ void gather8(float x0, float x1, int g0, float (&xa)[8]) {
#pragma unroll
    for (int i = 0; i < 8; i++) {
        int idx = g0 * 8 + i;
        float a = __shfl_sync(0xffffffffu, x0, idx & 31);
        float bsh = __shfl_sync(0xffffffffu, x1, idx & 31);
        xa[i] = (idx < 32) ? a : bsh;
    }
}

__device__ __forceinline__ void load_w_padded(const float* __restrict__ w, float2* sw) {
    for (int i = threadIdx.x; i < 256; i += blockDim.x) {
        int g = i >> 5, r = i & 31;
        sw[g * 33 + r] = ((const float2*)w)[i];
    }
}

// ---------------- qkv1: V only (layer-0 attention is identity) ----------------
__global__ void k_qkv1(const float* __restrict__ wv, const float* __restrict__ bv) {
    __shared__ float2 swv[264];
    __shared__ float sbv[64];
    load_w_padded(wv, swv);
    if (threadIdx.x < 64) sbv[threadIdx.x] = bv[threadIdx.x];
    __syncthreads();
    int n = (blockIdx.x * blockDim.x + threadIdx.x) >> 5;
    if (n >= NN) return;
    int lane = threadIdx.x & 31;
    int g0 = lane >> 2;
    int wbase = g0 * 33 + (lane & 3);
    const float* xr = &g_xall[(size_t)n * 256];
    float x0 = xr[lane], x1 = xr[lane + 32];
    float xa[8];
    gather8(x0, x1, g0, xa);
    float2 vv = ((const float2*)sbv)[lane];
#pragma unroll
    for (int i = 0; i < 8; i++) {
        float2 wvv = swv[wbase + i * 4];
        vv.x += xa[i] * wvv.x;  vv.y += xa[i] * wvv.y;
    }
    float dr = g_dis[n];
    g_V1[n * 32 + lane] = f2u(vv.x * dr, vv.y * dr);
}

// ---------------- qkv2: layers {0,1} K,V + Q(layer1), net-layer-1 weights ----------------
__global__ void k_qkv2(const float* __restrict__ wq, const float* __restrict__ bq,
                       const float* __restrict__ wk, const float* __restrict__ bk,
                       const float* __restrict__ wv, const float* __restrict__ bv) {
    __shared__ float2 swq[264], swk[264], swv[264];
    __shared__ float sbq[64], sbk[64], sbv[64];
    load_w_padded(wq, swq);
    load_w_padded(wk, swk);
    load_w_padded(wv, swv);
    if (threadIdx.x < 64) {
        sbq[threadIdx.x] = bq[threadIdx.x];
        sbk[threadIdx.x] = bk[threadIdx.x];
        sbv[threadIdx.x] = bv[threadIdx.x];
    }
    __syncthreads();
    int n = (blockIdx.x * blockDim.x + threadIdx.x) >> 5;
    if (n >= NN) return;
    int lane = threadIdx.x & 31;
    int g0 = lane >> 2;
    int wbase = g0 * 33 + (lane & 3);
    float dr = g_dis[n];
    const float* xr = &g_xall[(size_t)n * 256];

    uint4 pack;
    // layer 0
    {
        float x0 = xr[lane], x1 = xr[lane + 32];
        float xa[8];
        gather8(x0, x1, g0, xa);
        float2 kk = ((const float2*)sbk)[lane];
        float2 vv = ((const float2*)sbv)[lane];
#pragma unroll
        for (int i = 0; i < 8; i++) {
            float2 wkv = swk[wbase + i * 4];
            kk.x += xa[i] * wkv.x;  kk.y += xa[i] * wkv.y;
            float2 wvv = swv[wbase + i * 4];
            vv.x += xa[i] * wvv.x;  vv.y += xa[i] * wvv.y;
        }
        pack.x = f2u(kk.x, kk.y);
        pack.y = f2u(vv.x * dr, vv.y * dr);
    }
    // layer 1 (+Q)
    {
        float x0 = xr[64 + lane], x1 = xr[64 + lane + 32];
        float xa[8];
        gather8(x0, x1, g0, xa);
        float2 kk = ((const float2*)sbk)[lane];
        float2 vv = ((const float2*)sbv)[lane];
        float2 qq = ((const float2*)sbq)[lane];
#pragma unroll
        for (int i = 0; i < 8; i++) {
            float2 wkv = swk[wbase + i * 4];
            kk.x += xa[i] * wkv.x;  kk.y += xa[i] * wkv.y;
            float2 wvv = swv[wbase + i * 4];
            vv.x += xa[i] * wvv.x;  vv.y += xa[i] * wvv.y;
            float2 wqv = swq[wbase + i * 4];
            qq.x += xa[i] * wqv.x;  qq.y += xa[i] * wqv.y;
        }
        pack.z = f2u(kk.x, kk.y);
        pack.w = f2u(vv.x * dr, vv.y * dr);
        g_Q[n * 32 + lane] = make_float2(qq.x * SC, qq.y * SC);
    }
    g_KVab[n * 32 + lane] = pack;
}

// ---------------- qkv3: layers {0,1,2} K,V + Q(layer2), net-layer-2 weights ----------------
__global__ void k_qkv3(const float* __restrict__ wq, const float* __restrict__ bq,
                       const float* __restrict__ wk, const float* __restrict__ bk,
                       const float* __restrict__ wv, const float* __restrict__ bv) {
    __shared__ float2 swq[264], swk[264], swv[264];
    __shared__ float sbq[64], sbk[64], sbv[64];
    load_w_padded(wq, swq);
    load_w_padded(wk, swk);
    load_w_padded(wv, swv);
    if (threadIdx.x < 64) {
        sbq[threadIdx.x] = bq[threadIdx.x];
        sbk[threadIdx.x] = bk[threadIdx.x];
        sbv[threadIdx.x] = bv[threadIdx.x];
    }
    __syncthreads();
    int n = (blockIdx.x * blockDim.x + threadIdx.x) >> 5;
    if (n >= NN) return;
    int lane = threadIdx.x & 31;
    int g0 = lane >> 2;
    int wbase = g0 * 33 + (lane & 3);
    float dr = g_dis[n];
    const float* xr = &g_xall[(size_t)n * 256];

    unsigned kvu[6];
#pragma unroll
    for (int layer = 0; layer < 3; layer++) {
        float x0 = xr[layer * 64 + lane], x1 = xr[layer * 64 + lane + 32];
        float xa[8];
        gather8(x0, x1, g0, xa);
        float2 kk = ((const float2*)sbk)[lane];
        float2 vv = ((const float2*)sbv)[lane];
#pragma unroll
        for (int i = 0; i < 8; i++) {
            float2 wkv = swk[wbase + i * 4];
            kk.x += xa[i] * wkv.x;  kk.y += xa[i] * wkv.y;
            float2 wvv = swv[wbase + i * 4];
            vv.x += xa[i] * wvv.x;  vv.y += xa[i] * wvv.y;
        }
        kvu[layer * 2]     = f2u(kk.x, kk.y);
        kvu[layer * 2 + 1] = f2u(vv.x * dr, vv.y * dr);
        if (layer == 2) {
            float2 qq = ((const float2*)sbq)[lane];
#pragma unroll
            for (int i = 0; i < 8; i++) {
                float2 wqv = swq[wbase + i * 4];
                qq.x += xa[i] * wqv.x;  qq.y += xa[i] * wqv.y;
            }
            g_Q[n * 32 + lane] = make_float2(qq.x * SC, qq.y * SC);
        }
    }
    g_KVab[n * 32 + lane] = make_uint4(kvu[0], kvu[1], kvu[2], kvu[3]);
    g_KVc[n * 32 + lane]  = make_uint2(kvu[4], kvu[5]);
}

// ---------------- edge kernels ----------------
// layer 0: attention over single source layer == identity -> pure gather-sum
__global__ void k_edge1() {
    int c = (blockIdx.x * blockDim.x + threadIdx.x) >> 5;
    if (c >= NN) return;
    int lane = threadIdx.x & 31;
    float ax = 0.f, ay = 0.f;
    int j = g_off[c], end = g_off[c + 1];
    const unsigned* __restrict__ V1 = g_V1;
    for (; j + 4 <= end; j += 4) {
        int r0 = g_csr[j], r1 = g_csr[j + 1], r2 = g_csr[j + 2], r3 = g_csr[j + 3];
        unsigned u0 = V1[r0 * 32 + lane];
        unsigned u1 = V1[r1 * 32 + lane];
        unsigned u2 = V1[r2 * 32 + lane];
        unsigned u3 = V1[r3 * 32 + lane];
        float2 f0 = u2f(u0), f1 = u2f(u1), f2 = u2f(u2), f3 = u2f(u3);
        ax += (f0.x + f1.x) + (f2.x + f3.x);
        ay += (f0.y + f1.y) + (f2.y + f3.y);
    }
    for (; j < end; j++) {
        float2 f = u2f(V1[g_csr[j] * 32 + lane]);
        ax += f.x;  ay += f.y;
    }
    float dc = g_dis[c];
    float2* xo = (float2*)&g_xall[(size_t)c * 256 + 64];
    xo[lane] = make_float2(fmaxf(ax * dc, 0.f), fmaxf(ay * dc, 0.f));
}

__device__ __forceinline__ void acc2(uint4 d, float2 qv, float& ax, float& ay) {
    float2 k0 = u2f(d.x), v0 = u2f(d.y), k1 = u2f(d.z), v1 = u2f(d.w);
    float s0 = qv.x * k0.x + qv.y * k0.y;
    s0 += __shfl_xor_sync(0xffffffffu, s0, 1);
    s0 += __shfl_xor_sync(0xffffffffu, s0, 2);
    float s1 = qv.x * k1.x + qv.y * k1.y;
    s1 += __shfl_xor_sync(0xffffffffu, s1, 1);
    s1 += __shfl_xor_sync(0xffffffffu, s1, 2);
    float m = fmaxf(s0, s1);
    float e0 = __expf(s0 - m), e1 = __expf(s1 - m);
    float inv = __fdividef(1.0f, e0 + e1);
    ax += (e0 * v0.x + e1 * v1.x) * inv;
    ay += (e0 * v0.y + e1 * v1.y) * inv;
}

__global__ void k_edge2() {
    int c = (blockIdx.x * blockDim.x + threadIdx.x) >> 5;
    if (c >= NN) return;
    int lane = threadIdx.x & 31;
    float2 qv = g_Q[c * 32 + lane];
    float ax = 0.f, ay = 0.f;
    int j = g_off[c], end = g_off[c + 1];
    const uint4* __restrict__ KV = g_KVab;
    for (; j + 4 <= end; j += 4) {
        int r0 = g_csr[j], r1 = g_csr[j + 1], r2 = g_csr[j + 2], r3 = g_csr[j + 3];
        uint4 d0 = KV[r0 * 32 + lane];
        uint4 d1 = KV[r1 * 32 + lane];
        uint4 d2 = KV[r2 * 32 + lane];
        uint4 d3 = KV[r3 * 32 + lane];
        acc2(d0, qv, ax, ay);
        acc2(d1, qv, ax, ay);
        acc2(d2, qv, ax, ay);
        acc2(d3, qv, ax, ay);
    }
    for (; j < end; j++) {
        acc2(KV[g_csr[j] * 32 + lane], qv, ax, ay);
    }
    float dc = g_dis[c];
    float2* xo = (float2*)&g_xall[(size_t)c * 256 + 128];
    xo[lane] = make_float2(fmaxf(ax * dc, 0.f), fmaxf(ay * dc, 0.f));
}

__device__ __forceinline__ void acc3(uint4 d, uint2 e, float2 qv, float& ax, float& ay) {
    float2 k0 = u2f(d.x), v0 = u2f(d.y), k1 = u2f(d.z), v1 = u2f(d.w);
    float2 k2 = u2f(e.x), v2 = u2f(e.y);
    float s0 = qv.x * k0.x + qv.y * k0.y;
    s0 += __shfl_xor_sync(0xffffffffu, s0, 1);
    s0 += __shfl_xor_sync(0xffffffffu, s0, 2);
    float s1 = qv.x * k1.x + qv.y * k1.y;
    s1 += __shfl_xor_sync(0xffffffffu, s1, 1);
    s1 += __shfl_xor_sync(0xffffffffu, s1, 2);
    float s2 = qv.x * k2.x + qv.y * k2.y;
    s2 += __shfl_xor_sync(0xffffffffu, s2, 1);
    s2 += __shfl_xor_sync(0xffffffffu, s2, 2);
    float m = fmaxf(fmaxf(s0, s1), s2);
    float e0 = __expf(s0 - m), e1 = __expf(s1 - m), e2 = __expf(s2 - m);
    float inv = __fdividef(1.0f, e0 + e1 + e2);
    ax += (e0 * v0.x + e1 * v1.x + e2 * v2.x) * inv;
    ay += (e0 * v0.y + e1 * v1.y + e2 * v2.y) * inv;
}

__global__ void k_edge3() {
    int c = (blockIdx.x * blockDim.x + threadIdx.x) >> 5;
    if (c >= NN) return;
    int lane = threadIdx.x & 31;
    float2 qv = g_Q[c * 32 + lane];
    float ax = 0.f, ay = 0.f;
    int j = g_off[c], end = g_off[c + 1];
    const uint4* __restrict__ KVa = g_KVab;
    const uint2* __restrict__ KVc = g_KVc;
    for (; j + 4 <= end; j += 4) {
        int r0 = g_csr[j], r1 = g_csr[j + 1], r2 = g_csr[j + 2], r3 = g_csr[j + 3];
        uint4 d0 = KVa[r0 * 32 + lane];
        uint4 d1 = KVa[r1 * 32 + lane];
        uint4 d2 = KVa[r2 * 32 + lane];
        uint4 d3 = KVa[r3 * 32 + lane];
        uint2 e0 = KVc[r0 * 32 + lane];
        uint2 e1 = KVc[r1 * 32 + lane];
        uint2 e2 = KVc[r2 * 32 + lane];
        uint2 e3 = KVc[r3 * 32 + lane];
        acc3(d0, e0, qv, ax, ay);
        acc3(d1, e1, qv, ax, ay);
        acc3(d2, e2, qv, ax, ay);
        acc3(d3, e3, qv, ax, ay);
    }
    for (; j < end; j++) {
        int r = g_csr[j];
        acc3(KVa[r * 32 + lane], KVc[r * 32 + lane], qv, ax, ay);
    }
    float dc = g_dis[c];
    float2* xo = (float2*)&g_xall[(size_t)c * 256 + 192];
    xo[lane] = make_float2(fmaxf(ax * dc, 0.f), fmaxf(ay * dc, 0.f));
}

// ---------------- lin2 + log_softmax ----------------
__global__ void k_lin2(const float* __restrict__ w, const float* __restrict__ b,
                       float* __restrict__ out) {
    __shared__ float sw[2048];   // [64][32]
    __shared__ float sb[32];
    for (int i = threadIdx.x; i < 2048; i += blockDim.x) sw[i] = w[i];
    if (threadIdx.x < 32) sb[threadIdx.x] = b[threadIdx.x];
    __syncthreads();
    int n = (blockIdx.x * blockDim.x + threadIdx.x) >> 5;
    if (n >= NN) return;
    int lane = threadIdx.x & 31;   // lane = class
    float x0 = g_xall[(size_t)n * 256 + 192 + lane];
    float x1 = g_xall[(size_t)n * 256 + 192 + lane + 32];
    float acc = sb[lane];
#pragma unroll
    for (int k = 0; k < 32; k++) acc += __shfl_sync(0xffffffffu, x0, k) * sw[k * 32 + lane];
#pragma unroll
    for (int k = 0; k < 32; k++) acc += __shfl_sync(0xffffffffu, x1, k) * sw[(k + 32) * 32 + lane];
    float m = acc;
#pragma unroll
    for (int o = 16; o; o >>= 1) m = fmaxf(m, __shfl_xor_sync(0xffffffffu, m, o));
    float e = __expf(acc - m);
    float sum = e;
#pragma unroll
    for (int o = 16; o; o >>= 1) sum += __shfl_xor_sync(0xffffffffu, sum, o);
    out[(size_t)n * 32 + lane] = acc - m - logf(sum);
}

// ---------------- launch ----------------
extern "C" void kernel_launch(void* const* d_in, const int* in_sizes, int n_in,
                              void* d_out, int out_size) {
    const float* x  = (const float*)d_in[0];
    const int*   ei = (const int*)d_in[1];
    const float* w1 = (const float*)d_in[2];
    const float* b1 = (const float*)d_in[3];
    const float* wq = (const float*)d_in[4];
    const float* bq = (const float*)d_in[5];
    const float* wk = (const float*)d_in[6];
    const float* bk = (const float*)d_in[7];
    const float* wv = (const float*)d_in[8];
    const float* bv = (const float*)d_in[9];
    const float* w2 = (const float*)d_in[10];
    const float* b2 = (const float*)d_in[11];
    float* out = (float*)d_out;

    const int gridW = (NN * 32 + 255) / 256;            // warp-per-node kernels
    const int gridL1 = ((NN / 8) * 32 + 255) / 256;     // 8 nodes per warp

    // CSR + norm (single stream, serial)
    k_hist<<<(NE + 255) / 256, 256>>>(ei);       // launch 0
    k_scan<<<1, 1024>>>();                       // launch 1
    k_scatter<<<(EE + 255) / 256, 256>>>(ei);    // launch 2

    // encoder
    k_lin1<<<gridL1, 256>>>(x, w1, b1);          // launch 3

    // layer 0 (attention identity -> V-only)
    k_qkv1<<<gridW, 256>>>(wv, bv);              // launch 4
    k_edge1<<<gridW, 256>>>();                   // launch 5  <- ncu profiles this
    // layer 1
    k_qkv2<<<gridW, 256>>>(wq + 512, bq + 64, wk + 512, bk + 64, wv + 512, bv + 64);
    k_edge2<<<gridW, 256>>>();
    // layer 2
    k_qkv3<<<gridW, 256>>>(wq + 1024, bq + 128, wk + 1024, bk + 128, wv + 1024, bv + 128);
    k_edge3<<<gridW, 256>>>();

    // classifier
    k_lin2<<<gridW, 256>>>(w2, b2, out);
}

// round 9
// speedup vs baseline: 1.0839x; 1.0839x over previous
#include <cuda_runtime.h>
#include <cuda_fp16.h>

#define NN 25000
#define NE 400000
#define EE (NE + NN)          // 425000 (edges + self loops)
#define SC 0.35355339059327378f   // 1/sqrt(8)

// ---------------- scratch (static __device__, no allocs) ----------------
__device__ float    g_xall[NN * 4 * 64];   // x_all[N][4][64] fp32 (plain dim order)
__device__ float2   g_Q[NN * 32];          // per lane dims {2l,2l+1}, pre-scaled by SC
__device__ unsigned g_V1[NN * 32];         // layer-0 V as half2 {v.x*dis, v.y*dis}
__device__ uint4    g_KVab[NN * 32];       // {K_l0, V_l0, K_l1, V_l1} half2 each (V pre-scaled)
__device__ uint2    g_KVc[NN * 32];        // {K_l2, V_l2} half2 each (V pre-scaled)
__device__ float    g_dis[NN];
__device__ int      g_deg[NN];             // invariant: all-zero at kernel_launch entry
__device__ int      g_off[NN + 1];
__device__ int      g_cur[NN];
__device__ int      g_csr[EE];

__device__ __forceinline__ float2 u2f(unsigned u) {
    return __half22float2(*reinterpret_cast<const __half2*>(&u));
}
__device__ __forceinline__ unsigned f2u(float x, float y) {
    __half2 h = __floats2half2_rn(x, y);
    return *reinterpret_cast<unsigned*>(&h);
}

// ---------------- CSR build ----------------
__global__ void k_hist(const int* __restrict__ ei) {
    int e = blockIdx.x * blockDim.x + threadIdx.x;
    if (e < NE) atomicAdd(&g_deg[ei[NE + e]], 1);   // col = ei[1]; self loop implicit +1
}

// single-block scan over NN elements; also computes dis, seeds cur, resets deg
__global__ void k_scan() {
    __shared__ int wsum[32];
    int t = threadIdx.x;
    int lane = t & 31, wid = t >> 5;
    int i0 = t * 25;
    int i1 = i0 + 25 < NN ? i0 + 25 : NN;
    int s = 0;
    for (int i = i0; i < i1; i++) s += g_deg[i] + 1;   // +1 = self loop
    int inc = s;
#pragma unroll
    for (int o = 1; o < 32; o <<= 1) {
        int v = __shfl_up_sync(0xffffffffu, inc, o);
        if (lane >= o) inc += v;
    }
    if (lane == 31) wsum[wid] = inc;
    __syncthreads();
    if (t < 32) {
        int v = wsum[t];
        int inc2 = v;
#pragma unroll
        for (int o = 1; o < 32; o <<= 1) {
            int u = __shfl_up_sync(0xffffffffu, inc2, o);
            if (t >= o) inc2 += u;
        }
        wsum[t] = inc2 - v;   // exclusive
    }
    __syncthreads();
    int run = wsum[wid] + (inc - s);
    for (int i = i0; i < i1; i++) {
        int d = g_deg[i] + 1;
        g_off[i] = run;
        g_cur[i] = run;
        g_dis[i] = rsqrtf((float)d);
        g_deg[i] = 0;          // restore invariant for next replay
        run += d;
    }
    if (t == 0) g_off[NN] = EE;
}

__global__ void k_scatter(const int* __restrict__ ei) {
    int idx = blockIdx.x * blockDim.x + threadIdx.x;
    if (idx >= EE) return;
    int r, c;
    if (idx < NE) { r = ei[idx]; c = ei[NE + idx]; }
    else          { r = c = idx - NE; }               // self loop
    int p = atomicAdd(&g_cur[c], 1);
    g_csr[p] = r;
}

// ---------------- helpers ----------------
// gather lane's group inputs x[g0*8+i] from warp-held pair registers (h = dims {2l,2l+1})
__device__ __forceinline__ void gather_pair(float2 h, int g0, float (&xa)[8]) {
#pragma unroll
    for (int i = 0; i < 8; i += 2) {
        int src = g0 * 4 + (i >> 1);
        xa[i]     = __shfl_sync(0xffffffffu, h.x, src);
        xa[i + 1] = __shfl_sync(0xffffffffu, h.y, src);
    }
}

// gather lane's group inputs from scalar-held row (x0 = dim lane, x1 = dim lane+32)
__device__ __forceinline__ void gather8(float x0, float x1, int g0, float (&xa)[8]) {
#pragma unroll
    for (int i = 0; i < 8; i++) {
        int idx = g0 * 8 + i;
        float a = __shfl_sync(0xffffffffu, x0, idx & 31);
        float bsh = __shfl_sync(0xffffffffu, x1, idx & 31);
        xa[i] = (idx < 32) ? a : bsh;
    }
}

// [8][8][8] weights into padded smem (stride 33 float2 per group)
__device__ __forceinline__ void load_w_padded(const float* __restrict__ w, float2* sw) {
    for (int i = threadIdx.x; i < 256; i += blockDim.x) {
        int g = i >> 5, r = i & 31;
        sw[g * 33 + r] = ((const float2*)w)[i];
    }
}

__device__ __forceinline__ float2 glin(const float2* sw, const float* sb,
                                       const float (&xa)[8], int wbase, int lane) {
    float2 o = ((const float2*)sb)[lane];
#pragma unroll
    for (int i = 0; i < 8; i++) {
        float2 w = sw[wbase + i * 4];
        o.x += xa[i] * w.x;
        o.y += xa[i] * w.y;
    }
    return o;
}

// ---------------- fused lin1 (smem-tiled) + qkv1 (V only) ----------------
// block = 256 thr = 8 warps, 64 nodes/block (8 per warp); lane = out pair {2l,2l+1}
__global__ void k_lin1qkv1(const float* __restrict__ x, const float* __restrict__ w,
                           const float* __restrict__ b,
                           const float* __restrict__ wv0, const float* __restrict__ bv0) {
    __shared__ float4 sx[64][17];    // 64 nodes x 64 k (16 float4, +1 pad)
    __shared__ float2 swv[264];
    __shared__ float sbv[64];
    load_w_padded(wv0, swv);
    if (threadIdx.x < 64) sbv[threadIdx.x] = bv0[threadIdx.x];
    int t = threadIdx.x;
    int warp = t >> 5, lane = t & 31;
    int nodeBase = blockIdx.x * 64;
    const float4* __restrict__ X4 = (const float4*)x;
    const float2* __restrict__ W2 = (const float2*)w;   // [256][32] float2
    float2 acc[8];
#pragma unroll
    for (int n = 0; n < 8; n++) acc[n] = make_float2(0.f, 0.f);

    for (int k0 = 0; k0 < 256; k0 += 64) {
        __syncthreads();
        // stage 64 rows x 16 float4, coalesced
#pragma unroll
        for (int i = 0; i < 4; i++) {
            int idx = i * 256 + t;
            int row = idx >> 4, col = idx & 15;
            if (nodeBase + row < NN)
                sx[row][col] = X4[(size_t)(nodeBase + row) * 64 + (k0 >> 2) + col];
        }
        __syncthreads();
#pragma unroll 4
        for (int ks = 0; ks < 16; ks++) {
            int kw = (k0 + ks * 4) * 32 + lane;
            float2 w0 = W2[kw];
            float2 w1 = W2[kw + 32];
            float2 w2v = W2[kw + 64];
            float2 w3 = W2[kw + 96];
#pragma unroll
            for (int n = 0; n < 8; n++) {
                float4 xv = sx[warp * 8 + n][ks];
                acc[n].x = fmaf(xv.x, w0.x, fmaf(xv.y, w1.x,
                           fmaf(xv.z, w2v.x, fmaf(xv.w, w3.x, acc[n].x))));
                acc[n].y = fmaf(xv.x, w0.y, fmaf(xv.y, w1.y,
                           fmaf(xv.z, w2v.y, fmaf(xv.w, w3.y, acc[n].y))));
            }
        }
    }

    float2 bb = ((const float2*)b)[lane];
    int g0 = lane >> 2;
    int wbase = g0 * 33 + (lane & 3);
#pragma unroll
    for (int n = 0; n < 8; n++) {
        int node = nodeBase + warp * 8 + n;
        float2 h = make_float2(fmaxf(acc[n].x + bb.x, 0.f), fmaxf(acc[n].y + bb.y, 0.f));
        float xa[8];
        gather_pair(h, g0, xa);           // all lanes participate (no divergence)
        float2 vv = glin(swv, sbv, xa, wbase, lane);
        if (node < NN) {
            ((float2*)&g_xall[(size_t)node * 256])[lane] = h;
            float dr = g_dis[node];
            g_V1[node * 32 + lane] = f2u(vv.x * dr, vv.y * dr);
        }
    }
}

// ---------------- qkv2: layers {0,1} K,V + Q(layer1), net-layer-1 weights ----------------
__global__ void k_qkv2(const float* __restrict__ wq, const float* __restrict__ bq,
                       const float* __restrict__ wk, const float* __restrict__ bk,
                       const float* __restrict__ wv, const float* __restrict__ bv) {
    __shared__ float2 swq[264], swk[264], swv[264];
    __shared__ float sbq[64], sbk[64], sbv[64];
    load_w_padded(wq, swq);
    load_w_padded(wk, swk);
    load_w_padded(wv, swv);
    if (threadIdx.x < 64) {
        sbq[threadIdx.x] = bq[threadIdx.x];
        sbk[threadIdx.x] = bk[threadIdx.x];
        sbv[threadIdx.x] = bv[threadIdx.x];
    }
    __syncthreads();
    int n = (blockIdx.x * blockDim.x + threadIdx.x) >> 5;
    if (n >= NN) return;
    int lane = threadIdx.x & 31;
    int g0 = lane >> 2;
    int wbase = g0 * 33 + (lane & 3);
    float dr = g_dis[n];
    const float* xr = &g_xall[(size_t)n * 256];

    uint4 pack;
    // layer 0
    {
        float x0 = xr[lane], x1 = xr[lane + 32];
        float xa[8];
        gather8(x0, x1, g0, xa);
        float2 kk = glin(swk, sbk, xa, wbase, lane);
        float2 vv = glin(swv, sbv, xa, wbase, lane);
        pack.x = f2u(kk.x, kk.y);
        pack.y = f2u(vv.x * dr, vv.y * dr);
    }
    // layer 1 (+Q)
    {
        float x0 = xr[64 + lane], x1 = xr[64 + lane + 32];
        float xa[8];
        gather8(x0, x1, g0, xa);
        float2 kk = glin(swk, sbk, xa, wbase, lane);
        float2 vv = glin(swv, sbv, xa, wbase, lane);
        float2 qq = glin(swq, sbq, xa, wbase, lane);
        pack.z = f2u(kk.x, kk.y);
        pack.w = f2u(vv.x * dr, vv.y * dr);
        g_Q[n * 32 + lane] = make_float2(qq.x * SC, qq.y * SC);
    }
    g_KVab[n * 32 + lane] = pack;
}

// ---------------- qkv3: layers {0,1,2} K,V + Q(layer2), net-layer-2 weights ----------------
__global__ void k_qkv3(const float* __restrict__ wq, const float* __restrict__ bq,
                       const float* __restrict__ wk, const float* __restrict__ bk,
                       const float* __restrict__ wv, const float* __restrict__ bv) {
    __shared__ float2 swq[264], swk[264], swv[264];
    __shared__ float sbq[64], sbk[64], sbv[64];
    load_w_padded(wq, swq);
    load_w_padded(wk, swk);
    load_w_padded(wv, swv);
    if (threadIdx.x < 64) {
        sbq[threadIdx.x] = bq[threadIdx.x];
        sbk[threadIdx.x] = bk[threadIdx.x];
        sbv[threadIdx.x] = bv[threadIdx.x];
    }
    __syncthreads();
    int n = (blockIdx.x * blockDim.x + threadIdx.x) >> 5;
    if (n >= NN) return;
    int lane = threadIdx.x & 31;
    int g0 = lane >> 2;
    int wbase = g0 * 33 + (lane & 3);
    float dr = g_dis[n];
    const float* xr = &g_xall[(size_t)n * 256];

    unsigned kvu[6];
#pragma unroll
    for (int layer = 0; layer < 3; layer++) {
        float x0 = xr[layer * 64 + lane], x1 = xr[layer * 64 + lane + 32];
        float xa[8];
        gather8(x0, x1, g0, xa);
        float2 kk = glin(swk, sbk, xa, wbase, lane);
        float2 vv = glin(swv, sbv, xa, wbase, lane);
        kvu[layer * 2]     = f2u(kk.x, kk.y);
        kvu[layer * 2 + 1] = f2u(vv.x * dr, vv.y * dr);
        if (layer == 2) {
            float2 qq = glin(swq, sbq, xa, wbase, lane);
            g_Q[n * 32 + lane] = make_float2(qq.x * SC, qq.y * SC);
        }
    }
    g_KVab[n * 32 + lane] = make_uint4(kvu[0], kvu[1], kvu[2], kvu[3]);
    g_KVc[n * 32 + lane]  = make_uint2(kvu[4], kvu[5]);
}

// ---------------- edge kernels ----------------
// layer 0: attention over single source layer == identity -> pure gather-sum
__global__ void k_edge1() {
    int c = (blockIdx.x * blockDim.x + threadIdx.x) >> 5;
    if (c >= NN) return;
    int lane = threadIdx.x & 31;
    float ax = 0.f, ay = 0.f;
    int j = g_off[c], end = g_off[c + 1];
    const unsigned* __restrict__ V1 = g_V1;
    for (; j + 4 <= end; j += 4) {
        int r0 = g_csr[j], r1 = g_csr[j + 1], r2 = g_csr[j + 2], r3 = g_csr[j + 3];
        unsigned u0 = V1[r0 * 32 + lane];
        unsigned u1 = V1[r1 * 32 + lane];
        unsigned u2 = V1[r2 * 32 + lane];
        unsigned u3 = V1[r3 * 32 + lane];
        float2 f0 = u2f(u0), f1 = u2f(u1), f2 = u2f(u2), f3 = u2f(u3);
        ax += (f0.x + f1.x) + (f2.x + f3.x);
        ay += (f0.y + f1.y) + (f2.y + f3.y);
    }
    for (; j < end; j++) {
        float2 f = u2f(V1[g_csr[j] * 32 + lane]);
        ax += f.x;  ay += f.y;
    }
    float dc = g_dis[c];
    float2* xo = (float2*)&g_xall[(size_t)c * 256 + 64];
    xo[lane] = make_float2(fmaxf(ax * dc, 0.f), fmaxf(ay * dc, 0.f));
}

__device__ __forceinline__ void acc2(uint4 d, float2 qv, float& ax, float& ay) {
    float2 k0 = u2f(d.x), v0 = u2f(d.y), k1 = u2f(d.z), v1 = u2f(d.w);
    float s0 = qv.x * k0.x + qv.y * k0.y;
    s0 += __shfl_xor_sync(0xffffffffu, s0, 1);
    s0 += __shfl_xor_sync(0xffffffffu, s0, 2);
    float s1 = qv.x * k1.x + qv.y * k1.y;
    s1 += __shfl_xor_sync(0xffffffffu, s1, 1);
    s1 += __shfl_xor_sync(0xffffffffu, s1, 2);
    float m = fmaxf(s0, s1);
    float e0 = __expf(s0 - m), e1 = __expf(s1 - m);
    float inv = __fdividef(1.0f, e0 + e1);
    ax += (e0 * v0.x + e1 * v1.x) * inv;
    ay += (e0 * v0.y + e1 * v1.y) * inv;
}

__global__ void k_edge2() {
    int c = (blockIdx.x * blockDim.x + threadIdx.x) >> 5;
    if (c >= NN) return;
    int lane = threadIdx.x & 31;
    float2 qv = g_Q[c * 32 + lane];
    float ax = 0.f, ay = 0.f;
    int j = g_off[c], end = g_off[c + 1];
    const uint4* __restrict__ KV = g_KVab;
    for (; j + 4 <= end; j += 4) {
        int r0 = g_csr[j], r1 = g_csr[j + 1], r2 = g_csr[j + 2], r3 = g_csr[j + 3];
        uint4 d0 = KV[r0 * 32 + lane];
        uint4 d1 = KV[r1 * 32 + lane];
        uint4 d2 = KV[r2 * 32 + lane];
        uint4 d3 = KV[r3 * 32 + lane];
        acc2(d0, qv, ax, ay);
        acc2(d1, qv, ax, ay);
        acc2(d2, qv, ax, ay);
        acc2(d3, qv, ax, ay);
    }
    for (; j < end; j++) {
        acc2(KV[g_csr[j] * 32 + lane], qv, ax, ay);
    }
    float dc = g_dis[c];
    float2* xo = (float2*)&g_xall[(size_t)c * 256 + 128];
    xo[lane] = make_float2(fmaxf(ax * dc, 0.f), fmaxf(ay * dc, 0.f));
}

__device__ __forceinline__ void acc3(uint4 d, uint2 e, float2 qv, float& ax, float& ay) {
    float2 k0 = u2f(d.x), v0 = u2f(d.y), k1 = u2f(d.z), v1 = u2f(d.w);
    float2 k2 = u2f(e.x), v2 = u2f(e.y);
    float s0 = qv.x * k0.x + qv.y * k0.y;
    s0 += __shfl_xor_sync(0xffffffffu, s0, 1);
    s0 += __shfl_xor_sync(0xffffffffu, s0, 2);
    float s1 = qv.x * k1.x + qv.y * k1.y;
    s1 += __shfl_xor_sync(0xffffffffu, s1, 1);
    s1 += __shfl_xor_sync(0xffffffffu, s1, 2);
    float s2 = qv.x * k2.x + qv.y * k2.y;
    s2 += __shfl_xor_sync(0xffffffffu, s2, 1);
    s2 += __shfl_xor_sync(0xffffffffu, s2, 2);
    float m = fmaxf(fmaxf(s0, s1), s2);
    float e0 = __expf(s0 - m), e1 = __expf(s1 - m), e2 = __expf(s2 - m);
    float inv = __fdividef(1.0f, e0 + e1 + e2);
    ax += (e0 * v0.x + e1 * v1.x + e2 * v2.x) * inv;
    ay += (e0 * v0.y + e1 * v1.y + e2 * v2.y) * inv;
}

// ---------------- fused edge3 + lin2 + log_softmax ----------------
__global__ void k_edge3lin2(const float* __restrict__ w, const float* __restrict__ b,
                            float* __restrict__ out) {
    __shared__ float sw[2048];   // [64][32]
    __shared__ float sb[32];
    for (int i = threadIdx.x; i < 2048; i += blockDim.x) sw[i] = w[i];
    if (threadIdx.x < 32) sb[threadIdx.x] = b[threadIdx.x];
    __syncthreads();
    int c = (blockIdx.x * blockDim.x + threadIdx.x) >> 5;
    if (c >= NN) return;
    int lane = threadIdx.x & 31;
    float2 qv = g_Q[c * 32 + lane];
    float ax = 0.f, ay = 0.f;
    int j = g_off[c], end = g_off[c + 1];
    const uint4* __restrict__ KVa = g_KVab;
    const uint2* __restrict__ KVc = g_KVc;
    for (; j + 4 <= end; j += 4) {
        int r0 = g_csr[j], r1 = g_csr[j + 1], r2 = g_csr[j + 2], r3 = g_csr[j + 3];
        uint4 d0 = KVa[r0 * 32 + lane];
        uint4 d1 = KVa[r1 * 32 + lane];
        uint4 d2 = KVa[r2 * 32 + lane];
        uint4 d3 = KVa[r3 * 32 + lane];
        uint2 e0 = KVc[r0 * 32 + lane];
        uint2 e1 = KVc[r1 * 32 + lane];
        uint2 e2 = KVc[r2 * 32 + lane];
        uint2 e3 = KVc[r3 * 32 + lane];
        acc3(d0, e0, qv, ax, ay);
        acc3(d1, e1, qv, ax, ay);
        acc3(d2, e2, qv, ax, ay);
        acc3(d3, e3, qv, ax, ay);
    }
    for (; j < end; j++) {
        int r = g_csr[j];
        acc3(KVa[r * 32 + lane], KVc[r * 32 + lane], qv, ax, ay);
    }
    float dc = g_dis[c];
    float hx = fmaxf(ax * dc, 0.f), hy = fmaxf(ay * dc, 0.f);

    // lin2: lane = class; h dims {2lp, 2lp+1} live in lane lp
    float acc = sb[lane];
#pragma unroll
    for (int lp = 0; lp < 32; lp++) {
        float bx = __shfl_sync(0xffffffffu, hx, lp);
        float by = __shfl_sync(0xffffffffu, hy, lp);
        acc += bx * sw[(2 * lp) * 32 + lane] + by * sw[(2 * lp + 1) * 32 + lane];
    }
    float m = acc;
#pragma unroll
    for (int o = 16; o; o >>= 1) m = fmaxf(m, __shfl_xor_sync(0xffffffffu, m, o));
    float e = __expf(acc - m);
    float sum = e;
#pragma unroll
    for (int o = 16; o; o >>= 1) sum += __shfl_xor_sync(0xffffffffu, sum, o);
    out[(size_t)c * 32 + lane] = acc - m - logf(sum);
}

// ---------------- launch ----------------
extern "C" void kernel_launch(void* const* d_in, const int* in_sizes, int n_in,
                              void* d_out, int out_size) {
    const float* x  = (const float*)d_in[0];
    const int*   ei = (const int*)d_in[1];
    const float* w1 = (const float*)d_in[2];
    const float* b1 = (const float*)d_in[3];
    const float* wq = (const float*)d_in[4];
    const float* bq = (const float*)d_in[5];
    const float* wk = (const float*)d_in[6];
    const float* bk = (const float*)d_in[7];
    const float* wv = (const float*)d_in[8];
    const float* bv = (const float*)d_in[9];
    const float* w2 = (const float*)d_in[10];
    const float* b2 = (const float*)d_in[11];
    float* out = (float*)d_out;

    const int gridW = (NN * 32 + 255) / 256;   // warp-per-node kernels (exact: 25000 warps)
    const int gridT = (NN + 63) / 64;          // 64 nodes per block for lin1qkv1

    // CSR + norm (single stream, serial)
    k_hist<<<(NE + 255) / 256, 256>>>(ei);
    k_scan<<<1, 1024>>>();
    k_scatter<<<(EE + 255) / 256, 256>>>(ei);

    // encoder + layer-0 V (fused)
    k_lin1qkv1<<<gridT, 256>>>(x, w1, b1, wv, bv);

    // layer 0 (attention identity -> gather-sum)
    k_edge1<<<gridW, 256>>>();
    // layer 1
    k_qkv2<<<gridW, 256>>>(wq + 512, bq + 64, wk + 512, bk + 64, wv + 512, bv + 64);
    k_edge2<<<gridW, 256>>>();
    // layer 2
    k_qkv3<<<gridW, 256>>>(wq + 1024, bq + 128, wk + 1024, bk + 128, wv + 1024, bv + 128);
    // edge3 + classifier (fused)
    k_edge3lin2<<<gridW, 256>>>(w2, b2, out);
}

// round 10
// speedup vs baseline: 1.0915x; 1.0070x over previous
#include <cuda_runtime.h>
#include <cuda_fp16.h>

#define NN 25000
#define NE 400000
#define EE (NE + NN)          // 425000 (edges + self loops)
#define SC 0.35355339059327378f   // 1/sqrt(8)

// ---------------- scratch (static __device__, no allocs) ----------------
__device__ float    g_xall[NN * 4 * 64];   // x_all[N][4][64] fp32 (plain dim order)
__device__ float2   g_Q[NN * 32];          // per lane dims {2l,2l+1}, pre-scaled by SC
__device__ unsigned g_V1[NN * 32];         // layer-0 V as half2 {v.x*dis, v.y*dis}
__device__ uint4    g_KVab[NN * 32];       // {K_l0, V_l0, K_l1, V_l1} half2 each (V pre-scaled)
__device__ uint2    g_KVc[NN * 32];        // {K_l2, V_l2} half2 each (V pre-scaled)
__device__ float    g_dis[NN];
__device__ int      g_deg[NN];             // invariant: all-zero at kernel_launch entry
__device__ int      g_off[NN + 1];
__device__ int      g_cur[NN];
__device__ int      g_csr[EE];

__device__ __forceinline__ float2 u2f(unsigned u) {
    return __half22float2(*reinterpret_cast<const __half2*>(&u));
}
__device__ __forceinline__ unsigned f2u(float x, float y) {
    __half2 h = __floats2half2_rn(x, y);
    return *reinterpret_cast<unsigned*>(&h);
}

// ---------------- CSR build ----------------
__global__ void k_hist(const int* __restrict__ ei) {
    int e = blockIdx.x * blockDim.x + threadIdx.x;
    if (e < NE) atomicAdd(&g_deg[ei[NE + e]], 1);   // col = ei[1]; self loop implicit +1
}

// single-block scan over NN elements; also computes dis, seeds cur, resets deg
__global__ void k_scan() {
    __shared__ int wsum[32];
    int t = threadIdx.x;
    int lane = t & 31, wid = t >> 5;
    int i0 = t * 25;
    int i1 = i0 + 25 < NN ? i0 + 25 : NN;
    int s = 0;
    for (int i = i0; i < i1; i++) s += g_deg[i] + 1;   // +1 = self loop
    int inc = s;
#pragma unroll
    for (int o = 1; o < 32; o <<= 1) {
        int v = __shfl_up_sync(0xffffffffu, inc, o);
        if (lane >= o) inc += v;
    }
    if (lane == 31) wsum[wid] = inc;
    __syncthreads();
    if (t < 32) {
        int v = wsum[t];
        int inc2 = v;
#pragma unroll
        for (int o = 1; o < 32; o <<= 1) {
            int u = __shfl_up_sync(0xffffffffu, inc2, o);
            if (t >= o) inc2 += u;
        }
        wsum[t] = inc2 - v;   // exclusive
    }
    __syncthreads();
    int run = wsum[wid] + (inc - s);
    for (int i = i0; i < i1; i++) {
        int d = g_deg[i] + 1;
        g_off[i] = run;
        g_cur[i] = run;
        g_dis[i] = rsqrtf((float)d);
        g_deg[i] = 0;          // restore invariant for next replay
        run += d;
    }
    if (t == 0) g_off[NN] = EE;
}

__global__ void k_scatter(const int* __restrict__ ei) {
    int idx = blockIdx.x * blockDim.x + threadIdx.x;
    if (idx >= EE) return;
    int r, c;
    if (idx < NE) { r = ei[idx]; c = ei[NE + idx]; }
    else          { r = c = idx - NE; }               // self loop
    int p = atomicAdd(&g_cur[c], 1);
    g_csr[p] = r;
}

// ---------------- helpers ----------------
__device__ __forceinline__ void gather_pair(float2 h, int g0, float (&xa)[8]) {
#pragma unroll
    for (int i = 0; i < 8; i += 2) {
        int src = g0 * 4 + (i >> 1);
        xa[i]     = __shfl_sync(0xffffffffu, h.x, src);
        xa[i + 1] = __shfl_sync(0xffffffffu, h.y, src);
    }
}

__device__ __forceinline__ void gather8(float x0, float x1, int g0, float (&xa)[8]) {
#pragma unroll
    for (int i = 0; i < 8; i++) {
        int idx = g0 * 8 + i;
        float a = __shfl_sync(0xffffffffu, x0, idx & 31);
        float bsh = __shfl_sync(0xffffffffu, x1, idx & 31);
        xa[i] = (idx < 32) ? a : bsh;
    }
}

__device__ __forceinline__ void load_w_padded(const float* __restrict__ w, float2* sw) {
    for (int i = threadIdx.x; i < 256; i += blockDim.x) {
        int g = i >> 5, r = i & 31;
        sw[g * 33 + r] = ((const float2*)w)[i];
    }
}

__device__ __forceinline__ float2 glin(const float2* sw, const float* sb,
                                       const float (&xa)[8], int wbase, int lane) {
    float2 o = ((const float2*)sb)[lane];
#pragma unroll
    for (int i = 0; i < 8; i++) {
        float2 w = sw[wbase + i * 4];
        o.x += xa[i] * w.x;
        o.y += xa[i] * w.y;
    }
    return o;
}

// ---------------- fused lin1 (smem-tiled, double-buffered) + qkv1 (V only) ----------------
// block = 256 thr = 8 warps, 64 nodes/block (8 per warp); lane = out pair {2l,2l+1}
__global__ void k_lin1qkv1(const float* __restrict__ x, const float* __restrict__ w,
                           const float* __restrict__ b,
                           const float* __restrict__ wv0, const float* __restrict__ bv0) {
    __shared__ float4 sx[64][17];    // 64 nodes x 64 k (16 float4, +1 pad)
    __shared__ float2 swv[264];
    __shared__ float sbv[64];
    load_w_padded(wv0, swv);
    if (threadIdx.x < 64) sbv[threadIdx.x] = bv0[threadIdx.x];
    int t = threadIdx.x;
    int warp = t >> 5, lane = t & 31;
    int nodeBase = blockIdx.x * 64;
    const float4* __restrict__ X4 = (const float4*)x;   // 64 float4 per node
    const float2* __restrict__ W2 = (const float2*)w;   // [256][32] float2
    float2 acc[8];
#pragma unroll
    for (int n = 0; n < 8; n++) acc[n] = make_float2(0.f, 0.f);

    // staging geometry: thread t covers (row = t/4 + 16*i? ) -> use idx mapping
    int srow0 = t >> 2;          // 0..63, 4 threads per row
    int scol0 = (t & 3) * 4;     // 0,4,8,12 (each thread loads 4 consecutive float4)

    // prologue: tile 0 into registers
    float4 rbuf[4];
#pragma unroll
    for (int i = 0; i < 4; i++) {
        int node = nodeBase + srow0;
        rbuf[i] = (node < NN) ? X4[(size_t)node * 64 + scol0 + i]
                              : make_float4(0.f, 0.f, 0.f, 0.f);
    }

#pragma unroll
    for (int tile = 0; tile < 4; tile++) {
        __syncthreads();   // previous compute done reading smem
#pragma unroll
        for (int i = 0; i < 4; i++) sx[srow0][scol0 + i] = rbuf[i];
        __syncthreads();
        if (tile < 3) {
            // issue next tile's loads NOW — in flight during compute below
            int node = nodeBase + srow0;
#pragma unroll
            for (int i = 0; i < 4; i++)
                rbuf[i] = (node < NN) ? X4[(size_t)node * 64 + (tile + 1) * 16 + scol0 + i]
                                      : make_float4(0.f, 0.f, 0.f, 0.f);
        }
        int k0 = tile * 64;
#pragma unroll 4
        for (int ks = 0; ks < 16; ks++) {
            int kw = (k0 + ks * 4) * 32 + lane;
            float2 w0 = W2[kw];
            float2 w1 = W2[kw + 32];
            float2 w2v = W2[kw + 64];
            float2 w3 = W2[kw + 96];
#pragma unroll
            for (int n = 0; n < 8; n++) {
                float4 xv = sx[warp * 8 + n][ks];
                acc[n].x = fmaf(xv.x, w0.x, fmaf(xv.y, w1.x,
                           fmaf(xv.z, w2v.x, fmaf(xv.w, w3.x, acc[n].x))));
                acc[n].y = fmaf(xv.x, w0.y, fmaf(xv.y, w1.y,
                           fmaf(xv.z, w2v.y, fmaf(xv.w, w3.y, acc[n].y))));
            }
        }
    }

    float2 bb = ((const float2*)b)[lane];
    int g0 = lane >> 2;
    int wbase = g0 * 33 + (lane & 3);
#pragma unroll
    for (int n = 0; n < 8; n++) {
        int node = nodeBase + warp * 8 + n;
        float2 h = make_float2(fmaxf(acc[n].x + bb.x, 0.f), fmaxf(acc[n].y + bb.y, 0.f));
        float xa[8];
        gather_pair(h, g0, xa);           // all lanes participate (no divergence)
        float2 vv = glin(swv, sbv, xa, wbase, lane);
        if (node < NN) {
            ((float2*)&g_xall[(size_t)node * 256])[lane] = h;
            float dr = g_dis[node];
            g_V1[node * 32 + lane] = f2u(vv.x * dr, vv.y * dr);
        }
    }
}

// ---------------- qkv2: layers {0,1} K,V + Q(layer1), net-layer-1 weights ----------------
__global__ void k_qkv2(const float* __restrict__ wq, const float* __restrict__ bq,
                       const float* __restrict__ wk, const float* __restrict__ bk,
                       const float* __restrict__ wv, const float* __restrict__ bv) {
    __shared__ float2 swq[264], swk[264], swv[264];
    __shared__ float sbq[64], sbk[64], sbv[64];
    load_w_padded(wq, swq);
    load_w_padded(wk, swk);
    load_w_padded(wv, swv);
    if (threadIdx.x < 64) {
        sbq[threadIdx.x] = bq[threadIdx.x];
        sbk[threadIdx.x] = bk[threadIdx.x];
        sbv[threadIdx.x] = bv[threadIdx.x];
    }
    __syncthreads();
    int n = (blockIdx.x * blockDim.x + threadIdx.x) >> 5;
    if (n >= NN) return;
    int lane = threadIdx.x & 31;
    int g0 = lane >> 2;
    int wbase = g0 * 33 + (lane & 3);
    float dr = g_dis[n];
    const float* xr = &g_xall[(size_t)n * 256];

    uint4 pack;
    // layer 0
    {
        float x0 = xr[lane], x1 = xr[lane + 32];
        float xa[8];
        gather8(x0, x1, g0, xa);
        float2 kk = glin(swk, sbk, xa, wbase, lane);
        float2 vv = glin(swv, sbv, xa, wbase, lane);
        pack.x = f2u(kk.x, kk.y);
        pack.y = f2u(vv.x * dr, vv.y * dr);
    }
    // layer 1 (+Q)
    {
        float x0 = xr[64 + lane], x1 = xr[64 + lane + 32];
        float xa[8];
        gather8(x0, x1, g0, xa);
        float2 kk = glin(swk, sbk, xa, wbase, lane);
        float2 vv = glin(swv, sbv, xa, wbase, lane);
        float2 qq = glin(swq, sbq, xa, wbase, lane);
        pack.z = f2u(kk.x, kk.y);
        pack.w = f2u(vv.x * dr, vv.y * dr);
        g_Q[n * 32 + lane] = make_float2(qq.x * SC, qq.y * SC);
    }
    g_KVab[n * 32 + lane] = pack;
}

// ---------------- qkv3: layers {0,1,2} K,V + Q(layer2), net-layer-2 weights ----------------
__global__ void k_qkv3(const float* __restrict__ wq, const float* __restrict__ bq,
                       const float* __restrict__ wk, const float* __restrict__ bk,
                       const float* __restrict__ wv, const float* __restrict__ bv) {
    __shared__ float2 swq[264], swk[264], swv[264];
    __shared__ float sbq[64], sbk[64], sbv[64];
    load_w_padded(wq, swq);
    load_w_padded(wk, swk);
    load_w_padded(wv, swv);
    if (threadIdx.x < 64) {
        sbq[threadIdx.x] = bq[threadIdx.x];
        sbk[threadIdx.x] = bk[threadIdx.x];
        sbv[threadIdx.x] = bv[threadIdx.x];
    }
    __syncthreads();
    int n = (blockIdx.x * blockDim.x + threadIdx.x) >> 5;
    if (n >= NN) return;
    int lane = threadIdx.x & 31;
    int g0 = lane >> 2;
    int wbase = g0 * 33 + (lane & 3);
    float dr = g_dis[n];
    const float* xr = &g_xall[(size_t)n * 256];

    unsigned kvu[6];
#pragma unroll
    for (int layer = 0; layer < 3; layer++) {
        float x0 = xr[layer * 64 + lane], x1 = xr[layer * 64 + lane + 32];
        float xa[8];
        gather8(x0, x1, g0, xa);
        float2 kk = glin(swk, sbk, xa, wbase, lane);
        float2 vv = glin(swv, sbv, xa, wbase, lane);
        kvu[layer * 2]     = f2u(kk.x, kk.y);
        kvu[layer * 2 + 1] = f2u(vv.x * dr, vv.y * dr);
        if (layer == 2) {
            float2 qq = glin(swq, sbq, xa, wbase, lane);
            g_Q[n * 32 + lane] = make_float2(qq.x * SC, qq.y * SC);
        }
    }
    g_KVab[n * 32 + lane] = make_uint4(kvu[0], kvu[1], kvu[2], kvu[3]);
    g_KVc[n * 32 + lane]  = make_uint2(kvu[4], kvu[5]);
}

// ---------------- edge kernels ----------------
// layer 0: attention over single source layer == identity -> pure gather-sum
__global__ void k_edge1() {
    int c = (blockIdx.x * blockDim.x + threadIdx.x) >> 5;
    if (c >= NN) return;
    int lane = threadIdx.x & 31;
    float ax = 0.f, ay = 0.f;
    int j = g_off[c], end = g_off[c + 1];
    const unsigned* __restrict__ V1 = g_V1;
    for (; j + 4 <= end; j += 4) {
        int r0 = g_csr[j], r1 = g_csr[j + 1], r2 = g_csr[j + 2], r3 = g_csr[j + 3];
        unsigned u0 = V1[r0 * 32 + lane];
        unsigned u1 = V1[r1 * 32 + lane];
        unsigned u2 = V1[r2 * 32 + lane];
        unsigned u3 = V1[r3 * 32 + lane];
        float2 f0 = u2f(u0), f1 = u2f(u1), f2 = u2f(u2), f3 = u2f(u3);
        ax += (f0.x + f1.x) + (f2.x + f3.x);
        ay += (f0.y + f1.y) + (f2.y + f3.y);
    }
    for (; j < end; j++) {
        float2 f = u2f(V1[g_csr[j] * 32 + lane]);
        ax += f.x;  ay += f.y;
    }
    float dc = g_dis[c];
    float2* xo = (float2*)&g_xall[(size_t)c * 256 + 64];
    xo[lane] = make_float2(fmaxf(ax * dc, 0.f), fmaxf(ay * dc, 0.f));
}

__device__ __forceinline__ void acc2(uint4 d, float2 qv, float& ax, float& ay) {
    float2 k0 = u2f(d.x), v0 = u2f(d.y), k1 = u2f(d.z), v1 = u2f(d.w);
    float s0 = qv.x * k0.x + qv.y * k0.y;
    s0 += __shfl_xor_sync(0xffffffffu, s0, 1);
    s0 += __shfl_xor_sync(0xffffffffu, s0, 2);
    float s1 = qv.x * k1.x + qv.y * k1.y;
    s1 += __shfl_xor_sync(0xffffffffu, s1, 1);
    s1 += __shfl_xor_sync(0xffffffffu, s1, 2);
    float m = fmaxf(s0, s1);
    float e0 = __expf(s0 - m), e1 = __expf(s1 - m);
    float inv = __fdividef(1.0f, e0 + e1);
    ax += (e0 * v0.x + e1 * v1.x) * inv;
    ay += (e0 * v0.y + e1 * v1.y) * inv;
}

__global__ void k_edge2() {
    int c = (blockIdx.x * blockDim.x + threadIdx.x) >> 5;
    if (c >= NN) return;
    int lane = threadIdx.x & 31;
    float2 qv = g_Q[c * 32 + lane];
    float ax = 0.f, ay = 0.f;
    int j = g_off[c], end = g_off[c + 1];
    const uint4* __restrict__ KV = g_KVab;
    for (; j + 4 <= end; j += 4) {
        int r0 = g_csr[j], r1 = g_csr[j + 1], r2 = g_csr[j + 2], r3 = g_csr[j + 3];
        uint4 d0 = KV[r0 * 32 + lane];
        uint4 d1 = KV[r1 * 32 + lane];
        uint4 d2 = KV[r2 * 32 + lane];
        uint4 d3 = KV[r3 * 32 + lane];
        acc2(d0, qv, ax, ay);
        acc2(d1, qv, ax, ay);
        acc2(d2, qv, ax, ay);
        acc2(d3, qv, ax, ay);
    }
    for (; j < end; j++) {
        acc2(KV[g_csr[j] * 32 + lane], qv, ax, ay);
    }
    float dc = g_dis[c];
    float2* xo = (float2*)&g_xall[(size_t)c * 256 + 128];
    xo[lane] = make_float2(fmaxf(ax * dc, 0.f), fmaxf(ay * dc, 0.f));
}

__device__ __forceinline__ void acc3(uint4 d, uint2 e, float2 qv, float& ax, float& ay) {
    float2 k0 = u2f(d.x), v0 = u2f(d.y), k1 = u2f(d.z), v1 = u2f(d.w);
    float2 k2 = u2f(e.x), v2 = u2f(e.y);
    float s0 = qv.x * k0.x + qv.y * k0.y;
    s0 += __shfl_xor_sync(0xffffffffu, s0, 1);
    s0 += __shfl_xor_sync(0xffffffffu, s0, 2);
    float s1 = qv.x * k1.x + qv.y * k1.y;
    s1 += __shfl_xor_sync(0xffffffffu, s1, 1);
    s1 += __shfl_xor_sync(0xffffffffu, s1, 2);
    float s2 = qv.x * k2.x + qv.y * k2.y;
    s2 += __shfl_xor_sync(0xffffffffu, s2, 1);
    s2 += __shfl_xor_sync(0xffffffffu, s2, 2);
    float m = fmaxf(fmaxf(s0, s1), s2);
    float e0 = __expf(s0 - m), e1 = __expf(s1 - m), e2 = __expf(s2 - m);
    float inv = __fdividef(1.0f, e0 + e1 + e2);
    ax += (e0 * v0.x + e1 * v1.x + e2 * v2.x) * inv;
    ay += (e0 * v0.y + e1 * v1.y + e2 * v2.y) * inv;
}

// ---------------- fused edge3 + lin2 + log_softmax ----------------
__global__ void k_edge3lin2(const float* __restrict__ w, const float* __restrict__ b,
                            float* __restrict__ out) {
    __shared__ float sw[2048];   // [64][32]
    __shared__ float sb[32];
    for (int i = threadIdx.x; i < 2048; i += blockDim.x) sw[i] = w[i];
    if (threadIdx.x < 32) sb[threadIdx.x] = b[threadIdx.x];
    __syncthreads();
    int c = (blockIdx.x * blockDim.x + threadIdx.x) >> 5;
    if (c >= NN) return;
    int lane = threadIdx.x & 31;
    float2 qv = g_Q[c * 32 + lane];
    float ax = 0.f, ay = 0.f;
    int j = g_off[c], end = g_off[c + 1];
    const uint4* __restrict__ KVa = g_KVab;
    const uint2* __restrict__ KVc = g_KVc;
    for (; j + 4 <= end; j += 4) {
        int r0 = g_csr[j], r1 = g_csr[j + 1], r2 = g_csr[j + 2], r3 = g_csr[j + 3];
        uint4 d0 = KVa[r0 * 32 + lane];
        uint4 d1 = KVa[r1 * 32 + lane];
        uint4 d2 = KVa[r2 * 32 + lane];
        uint4 d3 = KVa[r3 * 32 + lane];
        uint2 e0 = KVc[r0 * 32 + lane];
        uint2 e1 = KVc[r1 * 32 + lane];
        uint2 e2 = KVc[r2 * 32 + lane];
        uint2 e3 = KVc[r3 * 32 + lane];
        acc3(d0, e0, qv, ax, ay);
        acc3(d1, e1, qv, ax, ay);
        acc3(d2, e2, qv, ax, ay);
        acc3(d3, e3, qv, ax, ay);
    }
    for (; j < end; j++) {
        int r = g_csr[j];
        acc3(KVa[r * 32 + lane], KVc[r * 32 + lane], qv, ax, ay);
    }
    float dc = g_dis[c];
    float hx = fmaxf(ax * dc, 0.f), hy = fmaxf(ay * dc, 0.f);

    // lin2: lane = class; h dims {2lp, 2lp+1} live in lane lp
    float acc = sb[lane];
#pragma unroll
    for (int lp = 0; lp < 32; lp++) {
        float bx = __shfl_sync(0xffffffffu, hx, lp);
        float by = __shfl_sync(0xffffffffu, hy, lp);
        acc += bx * sw[(2 * lp) * 32 + lane] + by * sw[(2 * lp + 1) * 32 + lane];
    }
    float m = acc;
#pragma unroll
    for (int o = 16; o; o >>= 1) m = fmaxf(m, __shfl_xor_sync(0xffffffffu, m, o));
    float e = __expf(acc - m);
    float sum = e;
#pragma unroll
    for (int o = 16; o; o >>= 1) sum += __shfl_xor_sync(0xffffffffu, sum, o);
    out[(size_t)c * 32 + lane] = acc - m - logf(sum);
}

// ---------------- launch ----------------
extern "C" void kernel_launch(void* const* d_in, const int* in_sizes, int n_in,
                              void* d_out, int out_size) {
    const float* x  = (const float*)d_in[0];
    const int*   ei = (const int*)d_in[1];
    const float* w1 = (const float*)d_in[2];
    const float* b1 = (const float*)d_in[3];
    const float* wq = (const float*)d_in[4];
    const float* bq = (const float*)d_in[5];
    const float* wk = (const float*)d_in[6];
    const float* bk = (const float*)d_in[7];
    const float* wv = (const float*)d_in[8];
    const float* bv = (const float*)d_in[9];
    const float* w2 = (const float*)d_in[10];
    const float* b2 = (const float*)d_in[11];
    float* out = (float*)d_out;

    const int gridW = (NN * 32 + 255) / 256;   // warp-per-node kernels
    const int gridT = (NN + 63) / 64;          // 64 nodes per block for lin1qkv1

    // CSR + norm (single stream, serial)
    k_hist<<<(NE + 255) / 256, 256>>>(ei);
    k_scan<<<1, 1024>>>();
    k_scatter<<<(EE + 255) / 256, 256>>>(ei);

    // encoder + layer-0 V (fused, double-buffered)
    k_lin1qkv1<<<gridT, 256>>>(x, w1, b1, wv, bv);

    // layer 0 (attention identity -> gather-sum)
    k_edge1<<<gridW, 256>>>();
    // layer 1
    k_qkv2<<<gridW, 256>>>(wq + 512, bq + 64, wk + 512, bk + 64, wv + 512, bv + 64);
    k_edge2<<<gridW, 256>>>();
    // layer 2
    k_qkv3<<<gridW, 256>>>(wq + 1024, bq + 128, wk + 1024, bk + 128, wv + 1024, bv + 128);
    // edge3 + classifier (fused)
    k_edge3lin2<<<gridW, 256>>>(w2, b2, out);
}

// round 11
// speedup vs baseline: 1.1120x; 1.0189x over previous
#include <cuda_runtime.h>
#include <cuda_fp16.h>

#define NN 25000
#define NE 400000
#define EE (NE + NN)          // 425000 (edges + self loops)
#define SC 0.35355339059327378f   // 1/sqrt(8)

// ---------------- scratch (static __device__, no allocs) ----------------
__device__ float2   g_x0[NN * 32];   // layer-0 h, pair layout (lane l = dims 2l,2l+1)
__device__ float2   g_x1[NN * 32];   // layer-1 out (pair layout)
__device__ float2   g_QA[NN * 32];   // Q after layer1 (pre-scaled by SC)
__device__ float2   g_QB[NN * 32];   // Q after layer2
__device__ unsigned g_V1[NN * 32];   // layer-0 V half2, pre-scaled by dis
__device__ uint4    g_KVA[NN * 32];  // {K_l0, V_l0*dis, K_l1, V_l1*dis} (layer-1 weights)
__device__ uint4    g_KVB[NN * 32];  // {K_l0, V_l0*dis, K_l1, V_l1*dis} (layer-2 weights)
__device__ uint2    g_KVc[NN * 32];  // {K_l2, V_l2*dis} (layer-2 weights)
__device__ float    g_dis[NN];
__device__ int      g_deg[NN];       // invariant: all-zero at kernel_launch entry
__device__ int      g_off[NN + 1];
__device__ int      g_cur[NN];
__device__ int      g_csr[EE];

__device__ __forceinline__ float2 u2f(unsigned u) {
    return __half22float2(*reinterpret_cast<const __half2*>(&u));
}
__device__ __forceinline__ unsigned f2u(float x, float y) {
    __half2 h = __floats2half2_rn(x, y);
    return *reinterpret_cast<unsigned*>(&h);
}

#define CP_ASYNC16(dst, src) \
    asm volatile("cp.async.cg.shared.global [%0], [%1], 16;" :: "r"(dst), "l"(src))
#define CP_COMMIT() asm volatile("cp.async.commit_group;")
#define CP_WAIT1()  asm volatile("cp.async.wait_group 1;")

// ---------------- CSR build ----------------
__global__ void k_hist(const int* __restrict__ ei) {
    int e = blockIdx.x * blockDim.x + threadIdx.x;
    if (e < NE) atomicAdd(&g_deg[ei[NE + e]], 1);   // col = ei[1]; self loop implicit +1
}

// single-block scan over NN elements; also computes dis, seeds cur, resets deg
__global__ void k_scan() {
    __shared__ int wsum[32];
    int t = threadIdx.x;
    int lane = t & 31, wid = t >> 5;
    int i0 = t * 25;
    int i1 = i0 + 25 < NN ? i0 + 25 : NN;
    int s = 0;
    for (int i = i0; i < i1; i++) s += g_deg[i] + 1;   // +1 = self loop
    int inc = s;
#pragma unroll
    for (int o = 1; o < 32; o <<= 1) {
        int v = __shfl_up_sync(0xffffffffu, inc, o);
        if (lane >= o) inc += v;
    }
    if (lane == 31) wsum[wid] = inc;
    __syncthreads();
    if (t < 32) {
        int v = wsum[t];
        int inc2 = v;
#pragma unroll
        for (int o = 1; o < 32; o <<= 1) {
            int u = __shfl_up_sync(0xffffffffu, inc2, o);
            if (t >= o) inc2 += u;
        }
        wsum[t] = inc2 - v;   // exclusive
    }
    __syncthreads();
    int run = wsum[wid] + (inc - s);
    for (int i = i0; i < i1; i++) {
        int d = g_deg[i] + 1;
        g_off[i] = run;
        g_cur[i] = run;
        g_dis[i] = rsqrtf((float)d);
        g_deg[i] = 0;          // restore invariant for next replay
        run += d;
    }
    if (t == 0) g_off[NN] = EE;
}

__global__ void k_scatter(const int* __restrict__ ei) {
    int idx = blockIdx.x * blockDim.x + threadIdx.x;
    if (idx >= EE) return;
    int r, c;
    if (idx < NE) { r = ei[idx]; c = ei[NE + idx]; }
    else          { r = c = idx - NE; }               // self loop
    int p = atomicAdd(&g_cur[c], 1);
    g_csr[p] = r;
}

// ---------------- helpers ----------------
// gather lane's group inputs x[g0*8+i] from warp-held pair registers (h = dims {2l,2l+1})
__device__ __forceinline__ void gather_pair(float2 h, int g0, float (&xa)[8]) {
#pragma unroll
    for (int i = 0; i < 8; i += 2) {
        int src = g0 * 4 + (i >> 1);
        xa[i]     = __shfl_sync(0xffffffffu, h.x, src);
        xa[i + 1] = __shfl_sync(0xffffffffu, h.y, src);
    }
}

// [8][8][8] weights into padded smem (stride 33 float2 per group)
__device__ __forceinline__ void load_w_padded(const float* __restrict__ w, float2* sw) {
    for (int i = threadIdx.x; i < 256; i += blockDim.x) {
        int g = i >> 5, r = i & 31;
        sw[g * 33 + r] = ((const float2*)w)[i];
    }
}

__device__ __forceinline__ float2 glin(const float2* sw, const float* sb,
                                       const float (&xa)[8], int wbase, int lane) {
    float2 o = ((const float2*)sb)[lane];
#pragma unroll
    for (int i = 0; i < 8; i++) {
        float2 w = sw[wbase + i * 4];
        o.x += xa[i] * w.x;
        o.y += xa[i] * w.y;
    }
    return o;
}

// ---------------- fused lin1 (cp.async pipelined) + qkv1 (V only) ----------------
// block = 256 thr = 8 warps, 64 nodes/block (8 per warp); lane = out pair {2l,2l+1}
__global__ void k_lin1qkv1(const float* __restrict__ x, const float* __restrict__ w,
                           const float* __restrict__ b,
                           const float* __restrict__ wv0, const float* __restrict__ bv0) {
    __shared__ float4 sx[2][64][16];   // double buffer: 2 x 64 nodes x 64 k (16 float4)
    __shared__ float2 swv[264];
    __shared__ float sbv[64];
    load_w_padded(wv0, swv);
    if (threadIdx.x < 64) sbv[threadIdx.x] = bv0[threadIdx.x];
    int t = threadIdx.x;
    int warp = t >> 5, lane = t & 31;
    int nodeBase = blockIdx.x * 64;
    const float4* __restrict__ X4 = (const float4*)x;   // 64 float4 per node
    const float2* __restrict__ W2 = (const float2*)w;   // [256][32] float2

    // staging geometry: 4 threads per row, 4 consecutive float4 per thread
    int srow = t >> 2;
    int scol = (t & 3) * 4;
    int node_s = nodeBase + srow;
    const float4* __restrict__ Xs = X4 + (size_t)node_s * 64 + scol;
    bool ld_ok = (node_s < NN);

    // prologue: issue tiles 0 and 1
#pragma unroll
    for (int tl = 0; tl < 2; tl++) {
        if (ld_ok) {
#pragma unroll
            for (int i = 0; i < 4; i++) {
                unsigned dst = (unsigned)__cvta_generic_to_shared(&sx[tl][srow][scol + i]);
                CP_ASYNC16(dst, Xs + tl * 16 + i);
            }
        }
        CP_COMMIT();
    }

    float2 acc[8];
#pragma unroll
    for (int n = 0; n < 8; n++) acc[n] = make_float2(0.f, 0.f);

#pragma unroll
    for (int tile = 0; tile < 4; tile++) {
        CP_WAIT1();           // tile's group complete (pending <= 1)
        __syncthreads();
        int buf = tile & 1;
        int k0 = tile * 64;
#pragma unroll 4
        for (int ks = 0; ks < 16; ks++) {
            int kw = (k0 + ks * 4) * 32 + lane;
            float2 w0 = W2[kw];
            float2 w1 = W2[kw + 32];
            float2 w2v = W2[kw + 64];
            float2 w3 = W2[kw + 96];
#pragma unroll
            for (int n = 0; n < 8; n++) {
                float4 xv = sx[buf][warp * 8 + n][ks];
                acc[n].x = fmaf(xv.x, w0.x, fmaf(xv.y, w1.x,
                           fmaf(xv.z, w2v.x, fmaf(xv.w, w3.x, acc[n].x))));
                acc[n].y = fmaf(xv.x, w0.y, fmaf(xv.y, w1.y,
                           fmaf(xv.z, w2v.y, fmaf(xv.w, w3.y, acc[n].y))));
            }
        }
        __syncthreads();      // all warps done reading this buffer
        if (tile + 2 < 4 && ld_ok) {
#pragma unroll
            for (int i = 0; i < 4; i++) {
                unsigned dst = (unsigned)__cvta_generic_to_shared(&sx[buf][srow][scol + i]);
                CP_ASYNC16(dst, Xs + (tile + 2) * 16 + i);
            }
        }
        CP_COMMIT();          // empty groups keep wait_group accounting aligned
    }

    float2 bb = ((const float2*)b)[lane];
    int g0 = lane >> 2;
    int wbase = g0 * 33 + (lane & 3);
#pragma unroll
    for (int n = 0; n < 8; n++) {
        int node = nodeBase + warp * 8 + n;
        float2 h = make_float2(fmaxf(acc[n].x + bb.x, 0.f), fmaxf(acc[n].y + bb.y, 0.f));
        float xa[8];
        gather_pair(h, g0, xa);           // all lanes participate (no divergence)
        float2 vv = glin(swv, sbv, xa, wbase, lane);
        if (node < NN) {
            g_x0[node * 32 + lane] = h;
            float dr = g_dis[node];
            g_V1[node * 32 + lane] = f2u(vv.x * dr, vv.y * dr);
        }
    }
}

// ---------------- fused edge1 (identity attention) + qkv2 ----------------
__global__ void k_edge1qkv2(const float* __restrict__ wq, const float* __restrict__ bq,
                            const float* __restrict__ wk, const float* __restrict__ bk,
                            const float* __restrict__ wv, const float* __restrict__ bv) {
    __shared__ float2 swq[264], swk[264], swv[264];
    __shared__ float sbq[64], sbk[64], sbv[64];
    load_w_padded(wq, swq);
    load_w_padded(wk, swk);
    load_w_padded(wv, swv);
    if (threadIdx.x < 64) {
        sbq[threadIdx.x] = bq[threadIdx.x];
        sbk[threadIdx.x] = bk[threadIdx.x];
        sbv[threadIdx.x] = bv[threadIdx.x];
    }
    __syncthreads();
    int c = (blockIdx.x * blockDim.x + threadIdx.x) >> 5;
    if (c >= NN) return;
    int lane = threadIdx.x & 31;
    float ax = 0.f, ay = 0.f;
    int j = g_off[c], end = g_off[c + 1];
    const unsigned* __restrict__ V1 = g_V1;
    for (; j + 4 <= end; j += 4) {
        int r0 = g_csr[j], r1 = g_csr[j + 1], r2 = g_csr[j + 2], r3 = g_csr[j + 3];
        unsigned u0 = V1[r0 * 32 + lane];
        unsigned u1 = V1[r1 * 32 + lane];
        unsigned u2 = V1[r2 * 32 + lane];
        unsigned u3 = V1[r3 * 32 + lane];
        float2 f0 = u2f(u0), f1 = u2f(u1), f2 = u2f(u2), f3 = u2f(u3);
        ax += (f0.x + f1.x) + (f2.x + f3.x);
        ay += (f0.y + f1.y) + (f2.y + f3.y);
    }
    for (; j < end; j++) {
        float2 f = u2f(V1[g_csr[j] * 32 + lane]);
        ax += f.x;  ay += f.y;
    }
    float dc = g_dis[c];
    float2 h1 = make_float2(fmaxf(ax * dc, 0.f), fmaxf(ay * dc, 0.f));
    g_x1[c * 32 + lane] = h1;

    // qkv2: layers {0,1} K,V + Q(layer1), with net-layer-1 weights
    int g0 = lane >> 2;
    int wbase = g0 * 33 + (lane & 3);
    float2 h0 = g_x0[c * 32 + lane];
    float xa[8];
    uint4 pack;
    gather_pair(h0, g0, xa);
    {
        float2 kk = glin(swk, sbk, xa, wbase, lane);
        float2 vv = glin(swv, sbv, xa, wbase, lane);
        pack.x = f2u(kk.x, kk.y);
        pack.y = f2u(vv.x * dc, vv.y * dc);
    }
    gather_pair(h1, g0, xa);
    {
        float2 kk = glin(swk, sbk, xa, wbase, lane);
        float2 vv = glin(swv, sbv, xa, wbase, lane);
        float2 qq = glin(swq, sbq, xa, wbase, lane);
        pack.z = f2u(kk.x, kk.y);
        pack.w = f2u(vv.x * dc, vv.y * dc);
        g_QA[c * 32 + lane] = make_float2(qq.x * SC, qq.y * SC);
    }
    g_KVA[c * 32 + lane] = pack;
}

// ---------------- attention accumulators ----------------
__device__ __forceinline__ void acc2(uint4 d, float2 qv, float& ax, float& ay) {
    float2 k0 = u2f(d.x), v0 = u2f(d.y), k1 = u2f(d.z), v1 = u2f(d.w);
    float s0 = qv.x * k0.x + qv.y * k0.y;
    s0 += __shfl_xor_sync(0xffffffffu, s0, 1);
    s0 += __shfl_xor_sync(0xffffffffu, s0, 2);
    float s1 = qv.x * k1.x + qv.y * k1.y;
    s1 += __shfl_xor_sync(0xffffffffu, s1, 1);
    s1 += __shfl_xor_sync(0xffffffffu, s1, 2);
    float m = fmaxf(s0, s1);
    float e0 = __expf(s0 - m), e1 = __expf(s1 - m);
    float inv = __fdividef(1.0f, e0 + e1);
    ax += (e0 * v0.x + e1 * v1.x) * inv;
    ay += (e0 * v0.y + e1 * v1.y) * inv;
}

__device__ __forceinline__ void acc3(uint4 d, uint2 e, float2 qv, float& ax, float& ay) {
    float2 k0 = u2f(d.x), v0 = u2f(d.y), k1 = u2f(d.z), v1 = u2f(d.w);
    float2 k2 = u2f(e.x), v2 = u2f(e.y);
    float s0 = qv.x * k0.x + qv.y * k0.y;
    s0 += __shfl_xor_sync(0xffffffffu, s0, 1);
    s0 += __shfl_xor_sync(0xffffffffu, s0, 2);
    float s1 = qv.x * k1.x + qv.y * k1.y;
    s1 += __shfl_xor_sync(0xffffffffu, s1, 1);
    s1 += __shfl_xor_sync(0xffffffffu, s1, 2);
    float s2 = qv.x * k2.x + qv.y * k2.y;
    s2 += __shfl_xor_sync(0xffffffffu, s2, 1);
    s2 += __shfl_xor_sync(0xffffffffu, s2, 2);
    float m = fmaxf(fmaxf(s0, s1), s2);
    float e0 = __expf(s0 - m), e1 = __expf(s1 - m), e2 = __expf(s2 - m);
    float inv = __fdividef(1.0f, e0 + e1 + e2);
    ax += (e0 * v0.x + e1 * v1.x + e2 * v2.x) * inv;
    ay += (e0 * v0.y + e1 * v1.y + e2 * v2.y) * inv;
}

// ---------------- fused edge2 + qkv3 ----------------
__global__ void k_edge2qkv3(const float* __restrict__ wq, const float* __restrict__ bq,
                            const float* __restrict__ wk, const float* __restrict__ bk,
                            const float* __restrict__ wv, const float* __restrict__ bv) {
    __shared__ float2 swq[264], swk[264], swv[264];
    __shared__ float sbq[64], sbk[64], sbv[64];
    load_w_padded(wq, swq);
    load_w_padded(wk, swk);
    load_w_padded(wv, swv);
    if (threadIdx.x < 64) {
        sbq[threadIdx.x] = bq[threadIdx.x];
        sbk[threadIdx.x] = bk[threadIdx.x];
        sbv[threadIdx.x] = bv[threadIdx.x];
    }
    __syncthreads();
    int c = (blockIdx.x * blockDim.x + threadIdx.x) >> 5;
    if (c >= NN) return;
    int lane = threadIdx.x & 31;
    float2 qv = g_QA[c * 32 + lane];
    float ax = 0.f, ay = 0.f;
    int j = g_off[c], end = g_off[c + 1];
    const uint4* __restrict__ KV = g_KVA;
    for (; j + 4 <= end; j += 4) {
        int r0 = g_csr[j], r1 = g_csr[j + 1], r2 = g_csr[j + 2], r3 = g_csr[j + 3];
        uint4 d0 = KV[r0 * 32 + lane];
        uint4 d1 = KV[r1 * 32 + lane];
        uint4 d2 = KV[r2 * 32 + lane];
        uint4 d3 = KV[r3 * 32 + lane];
        acc2(d0, qv, ax, ay);
        acc2(d1, qv, ax, ay);
        acc2(d2, qv, ax, ay);
        acc2(d3, qv, ax, ay);
    }
    for (; j < end; j++)
        acc2(KV[g_csr[j] * 32 + lane], qv, ax, ay);

    float dc = g_dis[c];
    float2 h2 = make_float2(fmaxf(ax * dc, 0.f), fmaxf(ay * dc, 0.f));
    // x2 never stored — consumed here in registers

    // qkv3: layers {0,1,2} K,V + Q(layer2), with net-layer-2 weights
    int g0 = lane >> 2;
    int wbase = g0 * 33 + (lane & 3);
    float xa[8];
    uint4 packA;
    gather_pair(g_x0[c * 32 + lane], g0, xa);
    {
        float2 kk = glin(swk, sbk, xa, wbase, lane);
        float2 vv = glin(swv, sbv, xa, wbase, lane);
        packA.x = f2u(kk.x, kk.y);
        packA.y = f2u(vv.x * dc, vv.y * dc);
    }
    gather_pair(g_x1[c * 32 + lane], g0, xa);
    {
        float2 kk = glin(swk, sbk, xa, wbase, lane);
        float2 vv = glin(swv, sbv, xa, wbase, lane);
        packA.z = f2u(kk.x, kk.y);
        packA.w = f2u(vv.x * dc, vv.y * dc);
    }
    g_KVB[c * 32 + lane] = packA;
    gather_pair(h2, g0, xa);
    {
        float2 kk = glin(swk, sbk, xa, wbase, lane);
        float2 vv = glin(swv, sbv, xa, wbase, lane);
        float2 qq = glin(swq, sbq, xa, wbase, lane);
        g_KVc[c * 32 + lane] = make_uint2(f2u(kk.x, kk.y), f2u(vv.x * dc, vv.y * dc));
        g_QB[c * 32 + lane] = make_float2(qq.x * SC, qq.y * SC);
    }
}

// ---------------- fused edge3 + lin2 + log_softmax ----------------
__global__ void k_edge3lin2(const float* __restrict__ w, const float* __restrict__ b,
                            float* __restrict__ out) {
    __shared__ float sw[2048];   // [64][32]
    __shared__ float sb[32];
    for (int i = threadIdx.x; i < 2048; i += blockDim.x) sw[i] = w[i];
    if (threadIdx.x < 32) sb[threadIdx.x] = b[threadIdx.x];
    __syncthreads();
    int c = (blockIdx.x * blockDim.x + threadIdx.x) >> 5;
    if (c >= NN) return;
    int lane = threadIdx.x & 31;
    float2 qv = g_QB[c * 32 + lane];
    float ax = 0.f, ay = 0.f;
    int j = g_off[c], end = g_off[c + 1];
    const uint4* __restrict__ KVa = g_KVB;
    const uint2* __restrict__ KVc = g_KVc;
    for (; j + 4 <= end; j += 4) {
        int r0 = g_csr[j], r1 = g_csr[j + 1], r2 = g_csr[j + 2], r3 = g_csr[j + 3];
        uint4 d0 = KVa[r0 * 32 + lane];
        uint4 d1 = KVa[r1 * 32 + lane];
        uint4 d2 = KVa[r2 * 32 + lane];
        uint4 d3 = KVa[r3 * 32 + lane];
        uint2 e0 = KVc[r0 * 32 + lane];
        uint2 e1 = KVc[r1 * 32 + lane];
        uint2 e2 = KVc[r2 * 32 + lane];
        uint2 e3 = KVc[r3 * 32 + lane];
        acc3(d0, e0, qv, ax, ay);
        acc3(d1, e1, qv, ax, ay);
        acc3(d2, e2, qv, ax, ay);
        acc3(d3, e3, qv, ax, ay);
    }
    for (; j < end; j++) {
        int r = g_csr[j];
        acc3(KVa[r * 32 + lane], KVc[r * 32 + lane], qv, ax, ay);
    }
    float dc = g_dis[c];
    float hx = fmaxf(ax * dc, 0.f), hy = fmaxf(ay * dc, 0.f);

    // lin2: lane = class; h dims {2lp, 2lp+1} live in lane lp
    float acc = sb[lane];
#pragma unroll
    for (int lp = 0; lp < 32; lp++) {
        float bx = __shfl_sync(0xffffffffu, hx, lp);
        float by = __shfl_sync(0xffffffffu, hy, lp);
        acc += bx * sw[(2 * lp) * 32 + lane] + by * sw[(2 * lp + 1) * 32 + lane];
    }
    float m = acc;
#pragma unroll
    for (int o = 16; o; o >>= 1) m = fmaxf(m, __shfl_xor_sync(0xffffffffu, m, o));
    float e = __expf(acc - m);
    float sum = e;
#pragma unroll
    for (int o = 16; o; o >>= 1) sum += __shfl_xor_sync(0xffffffffu, sum, o);
    out[(size_t)c * 32 + lane] = acc - m - logf(sum);
}

// ---------------- launch ----------------
extern "C" void kernel_launch(void* const* d_in, const int* in_sizes, int n_in,
                              void* d_out, int out_size) {
    const float* x  = (const float*)d_in[0];
    const int*   ei = (const int*)d_in[1];
    const float* w1 = (const float*)d_in[2];
    const float* b1 = (const float*)d_in[3];
    const float* wq = (const float*)d_in[4];
    const float* bq = (const float*)d_in[5];
    const float* wk = (const float*)d_in[6];
    const float* bk = (const float*)d_in[7];
    const float* wv = (const float*)d_in[8];
    const float* bv = (const float*)d_in[9];
    const float* w2 = (const float*)d_in[10];
    const float* b2 = (const float*)d_in[11];
    float* out = (float*)d_out;

    const int gridW = (NN * 32 + 255) / 256;   // warp-per-node kernels
    const int gridT = (NN + 63) / 64;          // 64 nodes per block for lin1qkv1

    // CSR + norm (single stream, serial)
    k_hist<<<(NE + 255) / 256, 256>>>(ei);
    k_scan<<<1, 1024>>>();
    k_scatter<<<(EE + 255) / 256, 256>>>(ei);

    // encoder + layer-0 V (fused, cp.async pipelined)    -> launch idx 3, ncu target
    k_lin1qkv1<<<gridT, 256>>>(x, w1, b1, wv, bv);

    // layer 0 edge (identity attention) + qkv for layer 1
    k_edge1qkv2<<<gridW, 256>>>(wq + 512, bq + 64, wk + 512, bk + 64, wv + 512, bv + 64);
    // layer 1 edge + qkv for layer 2
    k_edge2qkv3<<<gridW, 256>>>(wq + 1024, bq + 128, wk + 1024, bk + 128, wv + 1024, bv + 128);
    // layer 2 edge + classifier
    k_edge3lin2<<<gridW, 256>>>(w2, b2, out);
}

// round 12
// speedup vs baseline: 1.1212x; 1.0083x over previous
#include <cuda_runtime.h>
#include <cuda_fp16.h>

#define NN 25000
#define NE 400000
#define EE (NE + NN)          // 425000 (edges + self loops)
#define SC 0.35355339059327378f   // 1/sqrt(8)

// ---------------- scratch (static __device__, no allocs) ----------------
__device__ float2   g_x0[NN * 32];   // layer-0 h, pair layout (lane l = dims 2l,2l+1)
__device__ float2   g_x1[NN * 32];   // layer-1 out (pair layout)
__device__ float2   g_QA[NN * 32];   // Q after layer1 (pre-scaled by SC)
__device__ float2   g_QB[NN * 32];   // Q after layer2
__device__ unsigned g_V1[NN * 32];   // layer-0 V half2 (UNSCALED; dis applied in edge1)
__device__ uint4    g_KVA[NN * 32];  // {K_l0, V_l0*dis, K_l1, V_l1*dis} (layer-1 weights)
__device__ uint4    g_KVB[NN * 32];  // {K_l0, V_l0*dis, K_l1, V_l1*dis} (layer-2 weights)
__device__ uint2    g_KVc[NN * 32];  // {K_l2, V_l2*dis} (layer-2 weights)
__device__ float    g_dis[NN];
__device__ int      g_deg[NN];       // invariant: all-zero at kernel_launch entry
__device__ int      g_off[NN + 1];
__device__ int      g_cur[NN];
__device__ int      g_csr[EE];

__device__ __forceinline__ float2 u2f(unsigned u) {
    return __half22float2(*reinterpret_cast<const __half2*>(&u));
}
__device__ __forceinline__ unsigned f2u(float x, float y) {
    __half2 h = __floats2half2_rn(x, y);
    return *reinterpret_cast<unsigned*>(&h);
}

#define CP_ASYNC16(dst, src) \
    asm volatile("cp.async.cg.shared.global [%0], [%1], 16;" :: "r"(dst), "l"(src))
#define CP_COMMIT() asm volatile("cp.async.commit_group;")
#define CP_WAIT1()  asm volatile("cp.async.wait_group 1;")

// ---------------- CSR build ----------------
// single-block scan over NN elements; also computes dis, seeds cur, resets deg
__global__ void k_scan() {
    __shared__ int wsum[32];
    int t = threadIdx.x;
    int lane = t & 31, wid = t >> 5;
    int i0 = t * 25;
    int i1 = i0 + 25 < NN ? i0 + 25 : NN;
    int s = 0;
    for (int i = i0; i < i1; i++) s += g_deg[i] + 1;   // +1 = self loop
    int inc = s;
#pragma unroll
    for (int o = 1; o < 32; o <<= 1) {
        int v = __shfl_up_sync(0xffffffffu, inc, o);
        if (lane >= o) inc += v;
    }
    if (lane == 31) wsum[wid] = inc;
    __syncthreads();
    if (t < 32) {
        int v = wsum[t];
        int inc2 = v;
#pragma unroll
        for (int o = 1; o < 32; o <<= 1) {
            int u = __shfl_up_sync(0xffffffffu, inc2, o);
            if (t >= o) inc2 += u;
        }
        wsum[t] = inc2 - v;   // exclusive
    }
    __syncthreads();
    int run = wsum[wid] + (inc - s);
    for (int i = i0; i < i1; i++) {
        int d = g_deg[i] + 1;
        g_off[i] = run;
        g_cur[i] = run;
        g_dis[i] = rsqrtf((float)d);
        g_deg[i] = 0;          // restore invariant for next replay
        run += d;
    }
    if (t == 0) g_off[NN] = EE;
}

__global__ void k_scatter(const int* __restrict__ ei) {
    int idx = blockIdx.x * blockDim.x + threadIdx.x;
    if (idx >= EE) return;
    int r, c;
    if (idx < NE) { r = ei[idx]; c = ei[NE + idx]; }
    else          { r = c = idx - NE; }               // self loop
    int p = atomicAdd(&g_cur[c], 1);
    g_csr[p] = r;
}

// ---------------- helpers ----------------
// gather lane's group inputs x[g0*8+i] from warp-held pair registers (h = dims {2l,2l+1})
__device__ __forceinline__ void gather_pair(float2 h, int g0, float (&xa)[8]) {
#pragma unroll
    for (int i = 0; i < 8; i += 2) {
        int src = g0 * 4 + (i >> 1);
        xa[i]     = __shfl_sync(0xffffffffu, h.x, src);
        xa[i + 1] = __shfl_sync(0xffffffffu, h.y, src);
    }
}

// [8][8][8] weights into padded smem (stride 33 float2 per group)
__device__ __forceinline__ void load_w_padded(const float* __restrict__ w, float2* sw) {
    for (int i = threadIdx.x; i < 256; i += blockDim.x) {
        int g = i >> 5, r = i & 31;
        sw[g * 33 + r] = ((const float2*)w)[i];
    }
}

__device__ __forceinline__ float2 glin(const float2* sw, const float* sb,
                                       const float (&xa)[8], int wbase, int lane) {
    float2 o = ((const float2*)sb)[lane];
#pragma unroll
    for (int i = 0; i < 8; i++) {
        float2 w = sw[wbase + i * 4];
        o.x += xa[i] * w.x;
        o.y += xa[i] * w.y;
    }
    return o;
}

// ---------------- fused edge-histogram + lin1 (cp.async pipelined) + qkv1 ----------------
// block = 256 thr = 8 warps, 64 nodes/block (8 per warp); lane = out pair {2l,2l+1}
__global__ void k_lin1histqkv1(const float* __restrict__ x, const float* __restrict__ w,
                               const float* __restrict__ b,
                               const float* __restrict__ wv0, const float* __restrict__ bv0,
                               const int* __restrict__ ei) {
    __shared__ float4 sx[2][64][16];   // double buffer: 2 x 64 nodes x 64 k (16 float4)
    __shared__ float2 swv[264];
    __shared__ float sbv[64];
    int t = threadIdx.x;

    // edge histogram (independent work; atomics drain during the GEMM below)
    {
        int stride = gridDim.x * blockDim.x;
        for (int e = blockIdx.x * blockDim.x + t; e < NE; e += stride)
            atomicAdd(&g_deg[ei[NE + e]], 1);
    }

    load_w_padded(wv0, swv);
    if (t < 64) sbv[t] = bv0[t];
    int warp = t >> 5, lane = t & 31;
    int nodeBase = blockIdx.x * 64;
    const float4* __restrict__ X4 = (const float4*)x;   // 64 float4 per node
    const float2* __restrict__ W2 = (const float2*)w;   // [256][32] float2

    // staging geometry: 4 threads per row, 4 consecutive float4 per thread
    int srow = t >> 2;
    int scol = (t & 3) * 4;
    int node_s = nodeBase + srow;
    const float4* __restrict__ Xs = X4 + (size_t)node_s * 64 + scol;
    bool ld_ok = (node_s < NN);

    // prologue: issue tiles 0 and 1
#pragma unroll
    for (int tl = 0; tl < 2; tl++) {
        if (ld_ok) {
#pragma unroll
            for (int i = 0; i < 4; i++) {
                unsigned dst = (unsigned)__cvta_generic_to_shared(&sx[tl][srow][scol + i]);
                CP_ASYNC16(dst, Xs + tl * 16 + i);
            }
        }
        CP_COMMIT();
    }

    float2 acc[8];
#pragma unroll
    for (int n = 0; n < 8; n++) acc[n] = make_float2(0.f, 0.f);

#pragma unroll
    for (int tile = 0; tile < 4; tile++) {
        CP_WAIT1();           // tile's group complete (pending <= 1)
        __syncthreads();
        int buf = tile & 1;
        int k0 = tile * 64;
#pragma unroll 4
        for (int ks = 0; ks < 16; ks++) {
            int kw = (k0 + ks * 4) * 32 + lane;
            float2 w0 = W2[kw];
            float2 w1 = W2[kw + 32];
            float2 w2v = W2[kw + 64];
            float2 w3 = W2[kw + 96];
#pragma unroll
            for (int n = 0; n < 8; n++) {
                float4 xv = sx[buf][warp * 8 + n][ks];
                acc[n].x = fmaf(xv.x, w0.x, fmaf(xv.y, w1.x,
                           fmaf(xv.z, w2v.x, fmaf(xv.w, w3.x, acc[n].x))));
                acc[n].y = fmaf(xv.x, w0.y, fmaf(xv.y, w1.y,
                           fmaf(xv.z, w2v.y, fmaf(xv.w, w3.y, acc[n].y))));
            }
        }
        __syncthreads();      // all warps done reading this buffer
        if (tile + 2 < 4 && ld_ok) {
#pragma unroll
            for (int i = 0; i < 4; i++) {
                unsigned dst = (unsigned)__cvta_generic_to_shared(&sx[buf][srow][scol + i]);
                CP_ASYNC16(dst, Xs + (tile + 2) * 16 + i);
            }
        }
        CP_COMMIT();          // empty groups keep wait_group accounting aligned
    }

    float2 bb = ((const float2*)b)[lane];
    int g0 = lane >> 2;
    int wbase = g0 * 33 + (lane & 3);
#pragma unroll
    for (int n = 0; n < 8; n++) {
        int node = nodeBase + warp * 8 + n;
        float2 h = make_float2(fmaxf(acc[n].x + bb.x, 0.f), fmaxf(acc[n].y + bb.y, 0.f));
        float xa[8];
        gather_pair(h, g0, xa);           // all lanes participate (no divergence)
        float2 vv = glin(swv, sbv, xa, wbase, lane);
        if (node < NN) {
            g_x0[node * 32 + lane] = h;
            g_V1[node * 32 + lane] = f2u(vv.x, vv.y);   // unscaled; dis applied in edge1
        }
    }
}

// ---------------- fused edge1 (identity attention) + qkv2 ----------------
__global__ void k_edge1qkv2(const float* __restrict__ wq, const float* __restrict__ bq,
                            const float* __restrict__ wk, const float* __restrict__ bk,
                            const float* __restrict__ wv, const float* __restrict__ bv) {
    __shared__ float2 swq[264], swk[264], swv[264];
    __shared__ float sbq[64], sbk[64], sbv[64];
    load_w_padded(wq, swq);
    load_w_padded(wk, swk);
    load_w_padded(wv, swv);
    if (threadIdx.x < 64) {
        sbq[threadIdx.x] = bq[threadIdx.x];
        sbk[threadIdx.x] = bk[threadIdx.x];
        sbv[threadIdx.x] = bv[threadIdx.x];
    }
    __syncthreads();
    int c = (blockIdx.x * blockDim.x + threadIdx.x) >> 5;
    if (c >= NN) return;
    int lane = threadIdx.x & 31;
    float ax = 0.f, ay = 0.f;
    int j = g_off[c], end = g_off[c + 1];
    const unsigned* __restrict__ V1 = g_V1;
    for (; j + 4 <= end; j += 4) {
        int r0 = g_csr[j], r1 = g_csr[j + 1], r2 = g_csr[j + 2], r3 = g_csr[j + 3];
        unsigned u0 = V1[r0 * 32 + lane];
        unsigned u1 = V1[r1 * 32 + lane];
        unsigned u2 = V1[r2 * 32 + lane];
        unsigned u3 = V1[r3 * 32 + lane];
        float d0 = g_dis[r0], d1 = g_dis[r1], d2 = g_dis[r2], d3 = g_dis[r3];
        float2 f0 = u2f(u0), f1 = u2f(u1), f2 = u2f(u2), f3 = u2f(u3);
        ax += d0 * f0.x + d1 * f1.x + d2 * f2.x + d3 * f3.x;
        ay += d0 * f0.y + d1 * f1.y + d2 * f2.y + d3 * f3.y;
    }
    for (; j < end; j++) {
        int r = g_csr[j];
        float2 f = u2f(V1[r * 32 + lane]);
        float dr = g_dis[r];
        ax += dr * f.x;  ay += dr * f.y;
    }
    float dc = g_dis[c];
    float2 h1 = make_float2(fmaxf(ax * dc, 0.f), fmaxf(ay * dc, 0.f));
    g_x1[c * 32 + lane] = h1;

    // qkv2: layers {0,1} K,V + Q(layer1), with net-layer-1 weights
    int g0 = lane >> 2;
    int wbase = g0 * 33 + (lane & 3);
    float2 h0 = g_x0[c * 32 + lane];
    float xa[8];
    uint4 pack;
    gather_pair(h0, g0, xa);
    {
        float2 kk = glin(swk, sbk, xa, wbase, lane);
        float2 vv = glin(swv, sbv, xa, wbase, lane);
        pack.x = f2u(kk.x, kk.y);
        pack.y = f2u(vv.x * dc, vv.y * dc);
    }
    gather_pair(h1, g0, xa);
    {
        float2 kk = glin(swk, sbk, xa, wbase, lane);
        float2 vv = glin(swv, sbv, xa, wbase, lane);
        float2 qq = glin(swq, sbq, xa, wbase, lane);
        pack.z = f2u(kk.x, kk.y);
        pack.w = f2u(vv.x * dc, vv.y * dc);
        g_QA[c * 32 + lane] = make_float2(qq.x * SC, qq.y * SC);
    }
    g_KVA[c * 32 + lane] = pack;
}

// ---------------- attention accumulators ----------------
__device__ __forceinline__ void acc2(uint4 d, float2 qv, float& ax, float& ay) {
    float2 k0 = u2f(d.x), v0 = u2f(d.y), k1 = u2f(d.z), v1 = u2f(d.w);
    float s0 = qv.x * k0.x + qv.y * k0.y;
    s0 += __shfl_xor_sync(0xffffffffu, s0, 1);
    s0 += __shfl_xor_sync(0xffffffffu, s0, 2);
    float s1 = qv.x * k1.x + qv.y * k1.y;
    s1 += __shfl_xor_sync(0xffffffffu, s1, 1);
    s1 += __shfl_xor_sync(0xffffffffu, s1, 2);
    float m = fmaxf(s0, s1);
    float e0 = __expf(s0 - m), e1 = __expf(s1 - m);
    float inv = __fdividef(1.0f, e0 + e1);
    ax += (e0 * v0.x + e1 * v1.x) * inv;
    ay += (e0 * v0.y + e1 * v1.y) * inv;
}

__device__ __forceinline__ void acc3(uint4 d, uint2 e, float2 qv, float& ax, float& ay) {
    float2 k0 = u2f(d.x), v0 = u2f(d.y), k1 = u2f(d.z), v1 = u2f(d.w);
    float2 k2 = u2f(e.x), v2 = u2f(e.y);
    float s0 = qv.x * k0.x + qv.y * k0.y;
    s0 += __shfl_xor_sync(0xffffffffu, s0, 1);
    s0 += __shfl_xor_sync(0xffffffffu, s0, 2);
    float s1 = qv.x * k1.x + qv.y * k1.y;
    s1 += __shfl_xor_sync(0xffffffffu, s1, 1);
    s1 += __shfl_xor_sync(0xffffffffu, s1, 2);
    float s2 = qv.x * k2.x + qv.y * k2.y;
    s2 += __shfl_xor_sync(0xffffffffu, s2, 1);
    s2 += __shfl_xor_sync(0xffffffffu, s2, 2);
    float m = fmaxf(fmaxf(s0, s1), s2);
    float e0 = __expf(s0 - m), e1 = __expf(s1 - m), e2 = __expf(s2 - m);
    float inv = __fdividef(1.0f, e0 + e1 + e2);
    ax += (e0 * v0.x + e1 * v1.x + e2 * v2.x) * inv;
    ay += (e0 * v0.y + e1 * v1.y + e2 * v2.y) * inv;
}

// ---------------- fused edge2 + qkv3 ----------------
__global__ void k_edge2qkv3(const float* __restrict__ wq, const float* __restrict__ bq,
                            const float* __restrict__ wk, const float* __restrict__ bk,
                            const float* __restrict__ wv, const float* __restrict__ bv) {
    __shared__ float2 swq[264], swk[264], swv[264];
    __shared__ float sbq[64], sbk[64], sbv[64];
    load_w_padded(wq, swq);
    load_w_padded(wk, swk);
    load_w_padded(wv, swv);
    if (threadIdx.x < 64) {
        sbq[threadIdx.x] = bq[threadIdx.x];
        sbk[threadIdx.x] = bk[threadIdx.x];
        sbv[threadIdx.x] = bv[threadIdx.x];
    }
    __syncthreads();
    int c = (blockIdx.x * blockDim.x + threadIdx.x) >> 5;
    if (c >= NN) return;
    int lane = threadIdx.x & 31;
    float2 qv = g_QA[c * 32 + lane];
    float ax = 0.f, ay = 0.f;
    int j = g_off[c], end = g_off[c + 1];
    const uint4* __restrict__ KV = g_KVA;
    for (; j + 4 <= end; j += 4) {
        int r0 = g_csr[j], r1 = g_csr[j + 1], r2 = g_csr[j + 2], r3 = g_csr[j + 3];
        uint4 d0 = KV[r0 * 32 + lane];
        uint4 d1 = KV[r1 * 32 + lane];
        uint4 d2 = KV[r2 * 32 + lane];
        uint4 d3 = KV[r3 * 32 + lane];
        acc2(d0, qv, ax, ay);
        acc2(d1, qv, ax, ay);
        acc2(d2, qv, ax, ay);
        acc2(d3, qv, ax, ay);
    }
    for (; j < end; j++)
        acc2(KV[g_csr[j] * 32 + lane], qv, ax, ay);

    float dc = g_dis[c];
    float2 h2 = make_float2(fmaxf(ax * dc, 0.f), fmaxf(ay * dc, 0.f));
    // x2 never stored — consumed here in registers

    // qkv3: layers {0,1,2} K,V + Q(layer2), with net-layer-2 weights
    int g0 = lane >> 2;
    int wbase = g0 * 33 + (lane & 3);
    float xa[8];
    uint4 packA;
    gather_pair(g_x0[c * 32 + lane], g0, xa);
    {
        float2 kk = glin(swk, sbk, xa, wbase, lane);
        float2 vv = glin(swv, sbv, xa, wbase, lane);
        packA.x = f2u(kk.x, kk.y);
        packA.y = f2u(vv.x * dc, vv.y * dc);
    }
    gather_pair(g_x1[c * 32 + lane], g0, xa);
    {
        float2 kk = glin(swk, sbk, xa, wbase, lane);
        float2 vv = glin(swv, sbv, xa, wbase, lane);
        packA.z = f2u(kk.x, kk.y);
        packA.w = f2u(vv.x * dc, vv.y * dc);
    }
    g_KVB[c * 32 + lane] = packA;
    gather_pair(h2, g0, xa);
    {
        float2 kk = glin(swk, sbk, xa, wbase, lane);
        float2 vv = glin(swv, sbv, xa, wbase, lane);
        float2 qq = glin(swq, sbq, xa, wbase, lane);
        g_KVc[c * 32 + lane] = make_uint2(f2u(kk.x, kk.y), f2u(vv.x * dc, vv.y * dc));
        g_QB[c * 32 + lane] = make_float2(qq.x * SC, qq.y * SC);
    }
}

// ---------------- fused edge3 + lin2 + log_softmax ----------------
__global__ void k_edge3lin2(const float* __restrict__ w, const float* __restrict__ b,
                            float* __restrict__ out) {
    __shared__ float sw[2048];   // [64][32]
    __shared__ float sb[32];
    for (int i = threadIdx.x; i < 2048; i += blockDim.x) sw[i] = w[i];
    if (threadIdx.x < 32) sb[threadIdx.x] = b[threadIdx.x];
    __syncthreads();
    int c = (blockIdx.x * blockDim.x + threadIdx.x) >> 5;
    if (c >= NN) return;
    int lane = threadIdx.x & 31;
    float2 qv = g_QB[c * 32 + lane];
    float ax = 0.f, ay = 0.f;
    int j = g_off[c], end = g_off[c + 1];
    const uint4* __restrict__ KVa = g_KVB;
    const uint2* __restrict__ KVc = g_KVc;
    for (; j + 4 <= end; j += 4) {
        int r0 = g_csr[j], r1 = g_csr[j + 1], r2 = g_csr[j + 2], r3 = g_csr[j + 3];
        uint4 d0 = KVa[r0 * 32 + lane];
        uint4 d1 = KVa[r1 * 32 + lane];
        uint4 d2 = KVa[r2 * 32 + lane];
        uint4 d3 = KVa[r3 * 32 + lane];
        uint2 e0 = KVc[r0 * 32 + lane];
        uint2 e1 = KVc[r1 * 32 + lane];
        uint2 e2 = KVc[r2 * 32 + lane];
        uint2 e3 = KVc[r3 * 32 + lane];
        acc3(d0, e0, qv, ax, ay);
        acc3(d1, e1, qv, ax, ay);
        acc3(d2, e2, qv, ax, ay);
        acc3(d3, e3, qv, ax, ay);
    }
    for (; j < end; j++) {
        int r = g_csr[j];
        acc3(KVa[r * 32 + lane], KVc[r * 32 + lane], qv, ax, ay);
    }
    float dc = g_dis[c];
    float hx = fmaxf(ax * dc, 0.f), hy = fmaxf(ay * dc, 0.f);

    // lin2: lane = class; h dims {2lp, 2lp+1} live in lane lp
    float acc = sb[lane];
#pragma unroll
    for (int lp = 0; lp < 32; lp++) {
        float bx = __shfl_sync(0xffffffffu, hx, lp);
        float by = __shfl_sync(0xffffffffu, hy, lp);
        acc += bx * sw[(2 * lp) * 32 + lane] + by * sw[(2 * lp + 1) * 32 + lane];
    }
    float m = acc;
#pragma unroll
    for (int o = 16; o; o >>= 1) m = fmaxf(m, __shfl_xor_sync(0xffffffffu, m, o));
    float e = __expf(acc - m);
    float sum = e;
#pragma unroll
    for (int o = 16; o; o >>= 1) sum += __shfl_xor_sync(0xffffffffu, sum, o);
    out[(size_t)c * 32 + lane] = acc - m - logf(sum);
}

// ---------------- launch ----------------
extern "C" void kernel_launch(void* const* d_in, const int* in_sizes, int n_in,
                              void* d_out, int out_size) {
    const float* x  = (const float*)d_in[0];
    const int*   ei = (const int*)d_in[1];
    const float* w1 = (const float*)d_in[2];
    const float* b1 = (const float*)d_in[3];
    const float* wq = (const float*)d_in[4];
    const float* bq = (const float*)d_in[5];
    const float* wk = (const float*)d_in[6];
    const float* bk = (const float*)d_in[7];
    const float* wv = (const float*)d_in[8];
    const float* bv = (const float*)d_in[9];
    const float* w2 = (const float*)d_in[10];
    const float* b2 = (const float*)d_in[11];
    float* out = (float*)d_out;

    const int gridW = (NN * 32 + 255) / 256;   // warp-per-node kernels
    const int gridT = (NN + 63) / 64;          // 64 nodes per block for lin1

    // launch 0: encoder + layer-0 V + edge histogram (fused)
    k_lin1histqkv1<<<gridT, 256>>>(x, w1, b1, wv, bv, ei);
    // launch 1-2: CSR offsets + scatter
    k_scan<<<1, 1024>>>();
    k_scatter<<<(EE + 255) / 256, 256>>>(ei);

    // launch 3: layer-0 edge + qkv for layer 1   <- 4th launch: ncu target
    k_edge1qkv2<<<gridW, 256>>>(wq + 512, bq + 64, wk + 512, bk + 64, wv + 512, bv + 64);
    // launch 4: layer-1 edge + qkv for layer 2
    k_edge2qkv3<<<gridW, 256>>>(wq + 1024, bq + 128, wk + 1024, bk + 128, wv + 1024, bv + 128);
    // launch 5: layer-2 edge + classifier
    k_edge3lin2<<<gridW, 256>>>(w2, b2, out);
}